// round 2
// baseline (speedup 1.0000x reference)
#include <cuda_runtime.h>
#include <math.h>

#define BB 2
#define NA 2048
#define NATOMS (BB*NA)
#define BOXF 27.0f
#define SEL0 46
#define SEL1 92
#define ASEL0 16
#define ASEL1 32
#define NANG (ASEL0+ASEL1)      /* 48  */
#define NRAD (SEL0+SEL1)        /* 138 */
#define DDIM (NRAD + 3*NANG)    /* 282 */
#define HID 64
#define EPSF 1e-16f

__device__ float g_dist0[NATOMS*SEL0];
__device__ int   g_idx0 [NATOMS*SEL0];
__device__ float g_dist1[NATOMS*SEL1];
__device__ int   g_idx1 [NATOMS*SEL1];
__device__ float g_desc [NATOMS*DDIM];
__device__ float g_gdesc[NATOMS*DDIM];
__device__ float g_grad [NATOMS*3];
__device__ float g_e    [NATOMS];

__device__ __forceinline__ float mic(float d){
    return d - BOXF * rintf(d * (1.0f/BOXF));
}

// ---------------------------------------------------------------------------
// K1: per-atom sorted neighbor lists via bitonic sort of packed keys
// key = type(2b)<<43 | float_bits(dist)<<11 | idx(11b). self gets type=3.
// ---------------------------------------------------------------------------
__global__ void knn_kernel(const float* __restrict__ xyz, const int* __restrict__ types){
    __shared__ unsigned long long keys[NA];
    __shared__ int s_c0;
    int atom = blockIdx.x;
    int b = atom >> 11, i = atom & (NA-1);
    const float* xb = xyz + (size_t)b*NA*3;
    float xi = xb[3*i+0], yi = xb[3*i+1], zi = xb[3*i+2];
    int tid = threadIdx.x;

    for (int j = tid; j < NA; j += blockDim.x){
        float dx = mic(xi - xb[3*j+0] + EPSF);
        float dy = mic(yi - xb[3*j+1] + EPSF);
        float dz = mic(zi - xb[3*j+2] + EPSF);
        float d = sqrtf(dx*dx + dy*dy + dz*dz);
        unsigned t = (j == i) ? 3u : (unsigned)types[b*NA + j];
        keys[j] = ((unsigned long long)t << 43)
                | ((unsigned long long)__float_as_uint(d) << 11)
                | (unsigned long long)j;
    }
    __syncthreads();

    for (int k = 2; k <= NA; k <<= 1){
        for (int j = k >> 1; j > 0; j >>= 1){
            for (int m = tid; m < NA; m += blockDim.x){
                int l = m ^ j;
                if (l > m){
                    unsigned long long a = keys[m], c = keys[l];
                    bool swap = ((m & k) == 0) ? (a > c) : (a < c);
                    if (swap){ keys[m] = c; keys[l] = a; }
                }
            }
            __syncthreads();
        }
    }

    if (tid == 0){
        int lo = 0, hi = NA;
        while (lo < hi){
            int mid = (lo + hi) >> 1;
            if ((keys[mid] >> 43) == 0ULL) lo = mid + 1; else hi = mid;
        }
        s_c0 = lo;
    }
    __syncthreads();
    int c0 = s_c0;

    for (int m = tid; m < SEL0; m += blockDim.x){
        float d = INFINITY; int id = 0;
        if (m < c0){
            unsigned long long k64 = keys[m];
            d  = __uint_as_float((unsigned)((k64 >> 11) & 0xFFFFFFFFULL));
            id = (int)(k64 & 2047ULL);
        }
        g_dist0[(size_t)atom*SEL0 + m] = d;
        g_idx0 [(size_t)atom*SEL0 + m] = id;
    }
    for (int m = tid; m < SEL1; m += blockDim.x){
        float d = INFINITY; int id = 0;
        int src = c0 + m;
        if (src < NA && (keys[src] >> 43) == 1ULL){
            unsigned long long k64 = keys[src];
            d  = __uint_as_float((unsigned)((k64 >> 11) & 0xFFFFFFFFULL));
            id = (int)(k64 & 2047ULL);
        }
        g_dist1[(size_t)atom*SEL1 + m] = d;
        g_idx1 [(size_t)atom*SEL1 + m] = id;
    }
}

// ---------------------------------------------------------------------------
// Local frame (shared by desc forward and backward)
// ---------------------------------------------------------------------------
struct Frame {
    float r0x,r0y,r0z, r1x,r1y,r1z;
    float rv0x,rv0y,rv0z, rv1x,rv1y,rv1z;
    float d0, d1, inv0, inv1;
    float s, np, nc;
    float v2x,v2y,v2z, v3x,v3y,v3z;
    int j0, j1;
};

__device__ Frame make_frame(int atom, const float* xb, float xi, float yi, float zi){
    Frame f;
    float s00 = g_dist0[(size_t)atom*SEL0+0], s01 = g_dist0[(size_t)atom*SEL0+1];
    float s10 = g_dist1[(size_t)atom*SEL1+0], s11 = g_dist1[(size_t)atom*SEL1+1];
    int   i00 = g_idx0 [(size_t)atom*SEL0+0], i01 = g_idx0 [(size_t)atom*SEL0+1];
    int   i10 = g_idx1 [(size_t)atom*SEL1+0], i11 = g_idx1 [(size_t)atom*SEL1+1];
    if (s10 < s00){ f.d0 = s10; f.j0 = i10; } else { f.d0 = s00; f.j0 = i00; }
    if (s11 < s01){ f.d1 = s11; f.j1 = i11; } else { f.d1 = s01; f.j1 = i01; }

    f.rv0x = mic(xi - xb[3*f.j0+0] + EPSF);
    f.rv0y = mic(yi - xb[3*f.j0+1] + EPSF);
    f.rv0z = mic(zi - xb[3*f.j0+2] + EPSF);
    f.rv1x = mic(xi - xb[3*f.j1+0] + EPSF);
    f.rv1y = mic(yi - xb[3*f.j1+1] + EPSF);
    f.rv1z = mic(zi - xb[3*f.j1+2] + EPSF);

    f.inv0 = 1.0f/(f.d0 + EPSF);
    f.inv1 = 1.0f/(f.d1 + EPSF);
    f.r0x = f.rv0x*f.inv0; f.r0y = f.rv0y*f.inv0; f.r0z = f.rv0z*f.inv0;
    f.r1x = f.rv1x*f.inv1; f.r1y = f.rv1y*f.inv1; f.r1z = f.rv1z*f.inv1;

    f.s = f.r0x*f.r1x + f.r0y*f.r1y + f.r0z*f.r1z;
    float px = f.r1x - f.s*f.r0x;
    float py = f.r1y - f.s*f.r0y;
    float pz = f.r1z - f.s*f.r0z;
    f.np = sqrtf(px*px + py*py + pz*pz);
    float invnp = 1.0f/f.np;
    f.v2x = px*invnp; f.v2y = py*invnp; f.v2z = pz*invnp;

    float cx = f.r0y*f.r1z - f.r0z*f.r1y;
    float cy = f.r0z*f.r1x - f.r0x*f.r1z;
    float cz = f.r0x*f.r1y - f.r0y*f.r1x;
    f.nc = sqrtf(cx*cx + cy*cy + cz*cz);
    float invnc = 1.0f/f.nc;
    f.v3x = cx*invnc; f.v3y = cy*invnc; f.v3z = cz*invnc;
    return f;
}

// ---------------------------------------------------------------------------
// K2: descriptor forward (282 per atom)
// ---------------------------------------------------------------------------
__global__ void desc_kernel(const float* __restrict__ xyz){
    __shared__ float A[9];
    int atom = blockIdx.x;
    int b = atom >> 11, i = atom & (NA-1);
    const float* xb = xyz + (size_t)b*NA*3;
    float xi = xb[3*i+0], yi = xb[3*i+1], zi = xb[3*i+2];
    int tid = threadIdx.x;

    if (tid == 0){
        Frame f = make_frame(atom, xb, xi, yi, zi);
        A[0]=f.r0x; A[1]=f.r0y; A[2]=f.r0z;
        A[3]=f.v2x; A[4]=f.v2y; A[5]=f.v2z;
        A[6]=f.v3x; A[7]=f.v3y; A[8]=f.v3z;
    }
    __syncthreads();

    float* dsc = g_desc + (size_t)atom*DDIM;
    for (int m = tid; m < NRAD; m += blockDim.x){
        float s = (m < SEL0) ? g_dist0[(size_t)atom*SEL0 + m]
                             : g_dist1[(size_t)atom*SEL1 + (m - SEL0)];
        dsc[m] = 1.0f/(s + EPSF);
    }
    for (int k = tid; k < NANG; k += blockDim.x){
        int j; float d;
        if (k < ASEL0){ j = g_idx0[(size_t)atom*SEL0 + k]; d = g_dist0[(size_t)atom*SEL0 + k]; }
        else          { j = g_idx1[(size_t)atom*SEL1 + (k-ASEL0)]; d = g_dist1[(size_t)atom*SEL1 + (k-ASEL0)]; }
        float rx = mic(xi - xb[3*j+0] + EPSF);
        float ry = mic(yi - xb[3*j+1] + EPSF);
        float rz = mic(zi - xb[3*j+2] + EPSF);
        float inv = 1.0f/(d + EPSF);
        float w = inv*inv;
        dsc[NRAD + 3*k + 0] = (A[0]*rx + A[1]*ry + A[2]*rz)*w;
        dsc[NRAD + 3*k + 1] = (A[3]*rx + A[4]*ry + A[5]*rz)*w;
        dsc[NRAD + 3*k + 2] = (A[6]*rx + A[7]*ry + A[8]*rz)*w;
    }
}

// ---------------------------------------------------------------------------
// K3: MLP forward + backward (fused), per atom
// ---------------------------------------------------------------------------
__global__ void mlp_kernel(const int* __restrict__ types,
    const float* __restrict__ W00, const float* __restrict__ b00,
    const float* __restrict__ W01, const float* __restrict__ b01,
    const float* __restrict__ W02, const float* __restrict__ b02,
    const float* __restrict__ W10, const float* __restrict__ b10,
    const float* __restrict__ W11, const float* __restrict__ b11,
    const float* __restrict__ W12, const float* __restrict__ b12){

    __shared__ float sd[DDIM];
    __shared__ float h1s[HID], gz[HID], red[HID];
    int atom = blockIdx.x;
    int tid = threadIdx.x;
    int t = types[atom];
    const float* W0 = t ? W10 : W00; const float* B0 = t ? b10 : b00;
    const float* W1 = t ? W11 : W01; const float* B1 = t ? b11 : b01;
    const float* W2 = t ? W12 : W02; const float* B2 = t ? b12 : b02;

    const float* dsc = g_desc + (size_t)atom*DDIM;
    for (int d = tid; d < DDIM; d += HID) sd[d] = dsc[d];
    __syncthreads();

    float acc = B0[tid];
    for (int d = 0; d < DDIM; d++) acc += sd[d] * W0[d*HID + tid];
    float h1v = tanhf(acc);
    h1s[tid] = h1v;
    __syncthreads();

    acc = B1[tid];
    for (int s = 0; s < HID; s++) acc += h1s[s] * W1[s*HID + tid];
    float h2v = tanhf(acc);
    float w2  = W2[tid];
    red[tid] = h2v * w2;
    __syncthreads();
    for (int off = HID/2; off > 0; off >>= 1){
        if (tid < off) red[tid] += red[tid + off];
        __syncthreads();
    }
    if (tid == 0) g_e[atom] = red[0] + B2[0];

    // backward
    gz[tid] = w2 * (1.0f - h2v*h2v);
    __syncthreads();
    float gh1 = 0.0f;
    for (int s = 0; s < HID; s++) gh1 += W1[tid*HID + s] * gz[s];
    __syncthreads();
    gz[tid] = gh1 * (1.0f - h1v*h1v);
    __syncthreads();

    float* gout = g_gdesc + (size_t)atom*DDIM;
    for (int d = tid; d < DDIM; d += HID){
        float g = 0.0f;
        for (int s = 0; s < HID; s++) g += W0[d*HID + s] * gz[s];
        gout[d] = g;
    }
}

// ---------------------------------------------------------------------------
// K4: backward through descriptors -> position gradients (atomic scatter)
// ---------------------------------------------------------------------------
__global__ void bwd_kernel(const float* __restrict__ xyz){
    __shared__ float A[9];
    __shared__ float G[9];
    __shared__ float gi[3];
    int atom = blockIdx.x;
    int b = atom >> 11, i = atom & (NA-1);
    const float* xb = xyz + (size_t)b*NA*3;
    float xi = xb[3*i+0], yi = xb[3*i+1], zi = xb[3*i+2];
    int tid = threadIdx.x;

    Frame f;
    if (tid == 0){
        f = make_frame(atom, xb, xi, yi, zi);
        A[0]=f.r0x; A[1]=f.r0y; A[2]=f.r0z;
        A[3]=f.v2x; A[4]=f.v2y; A[5]=f.v2z;
        A[6]=f.v3x; A[7]=f.v3y; A[8]=f.v3z;
    }
    if (tid < 9) G[tid] = 0.0f;
    if (tid < 3) gi[tid] = 0.0f;
    __syncthreads();

    const float* gd = g_gdesc + (size_t)atom*DDIM;
    float* gradb = g_grad + (size_t)b*NA*3;

    // angular part
    if (tid < NANG){
        int k = tid;
        int j; float dN;
        if (k < ASEL0){ j = g_idx0[(size_t)atom*SEL0 + k]; dN = g_dist0[(size_t)atom*SEL0 + k]; }
        else          { j = g_idx1[(size_t)atom*SEL1 + (k-ASEL0)]; dN = g_dist1[(size_t)atom*SEL1 + (k-ASEL0)]; }
        float rx = mic(xi - xb[3*j+0] + EPSF);
        float ry = mic(yi - xb[3*j+1] + EPSF);
        float rz = mic(zi - xb[3*j+2] + EPSF);
        float gx = gd[NRAD + 3*k + 0];
        float gy = gd[NRAD + 3*k + 1];
        float gz3= gd[NRAD + 3*k + 2];
        float inv = 1.0f/(dN + EPSF);
        float w = inv*inv;
        float Arx = A[0]*rx + A[1]*ry + A[2]*rz;
        float Ary = A[3]*rx + A[4]*ry + A[5]*rz;
        float Arz = A[6]*rx + A[7]*ry + A[8]*rz;
        // de/drvec (direct) = w * A^T g
        float gvx = (A[0]*gx + A[3]*gy + A[6]*gz3)*w;
        float gvy = (A[1]*gx + A[4]*gy + A[7]*gz3)*w;
        float gvz = (A[2]*gx + A[5]*gy + A[8]*gz3)*w;
        // de/dd through w = 1/(d+eps)^2
        float gdd = (gx*Arx + gy*Ary + gz3*Arz) * (-2.0f*w*inv);
        // grad wrt A
        atomicAdd(&G[0], w*gx*rx);  atomicAdd(&G[1], w*gx*ry);  atomicAdd(&G[2], w*gx*rz);
        atomicAdd(&G[3], w*gy*rx);  atomicAdd(&G[4], w*gy*ry);  atomicAdd(&G[5], w*gy*rz);
        atomicAdd(&G[6], w*gz3*rx); atomicAdd(&G[7], w*gz3*ry); atomicAdd(&G[8], w*gz3*rz);
        float cf = gdd / dN;
        float gtx = gvx + cf*rx, gty = gvy + cf*ry, gtz = gvz + cf*rz;
        atomicAdd(&gi[0], gtx); atomicAdd(&gi[1], gty); atomicAdd(&gi[2], gtz);
        atomicAdd(&gradb[3*j+0], -gtx);
        atomicAdd(&gradb[3*j+1], -gty);
        atomicAdd(&gradb[3*j+2], -gtz);
    }

    // radial part
    for (int m = tid; m < NRAD; m += blockDim.x){
        int j; float s;
        if (m < SEL0){ j = g_idx0[(size_t)atom*SEL0 + m]; s = g_dist0[(size_t)atom*SEL0 + m]; }
        else         { j = g_idx1[(size_t)atom*SEL1 + (m-SEL0)]; s = g_dist1[(size_t)atom*SEL1 + (m-SEL0)]; }
        float gR = gd[m];
        float invr = 1.0f/(s + EPSF);
        float cf = -gR*invr*invr / s;
        float rx = mic(xi - xb[3*j+0] + EPSF);
        float ry = mic(yi - xb[3*j+1] + EPSF);
        float rz = mic(zi - xb[3*j+2] + EPSF);
        float gtx = cf*rx, gty = cf*ry, gtz = cf*rz;
        atomicAdd(&gi[0], gtx); atomicAdd(&gi[1], gty); atomicAdd(&gi[2], gtz);
        atomicAdd(&gradb[3*j+0], -gtx);
        atomicAdd(&gradb[3*j+1], -gty);
        atomicAdd(&gradb[3*j+2], -gtz);
    }
    __syncthreads();

    // frame backward (thread 0)
    if (tid == 0){
        float g0x=G[0], g0y=G[1], g0z=G[2];
        float g1x=G[3], g1y=G[4], g1z=G[5];
        float g2x=G[6], g2y=G[7], g2z=G[8];

        float dr0x = g0x, dr0y = g0y, dr0z = g0z;
        float dr1x = 0.f, dr1y = 0.f, dr1z = 0.f;

        // v2 = normalize(p), p = r1 - s*r0
        float t1 = g1x*f.v2x + g1y*f.v2y + g1z*f.v2z;
        float invnp = 1.0f/f.np;
        float gpx = (g1x - t1*f.v2x)*invnp;
        float gpy = (g1y - t1*f.v2y)*invnp;
        float gpz = (g1z - t1*f.v2z)*invnp;
        float gpr0 = gpx*f.r0x + gpy*f.r0y + gpz*f.r0z;
        dr1x += gpx - gpr0*f.r0x;
        dr1y += gpy - gpr0*f.r0y;
        dr1z += gpz - gpr0*f.r0z;
        dr0x += -f.s*gpx - gpr0*f.r1x;
        dr0y += -f.s*gpy - gpr0*f.r1y;
        dr0z += -f.s*gpz - gpr0*f.r1z;

        // v3 = normalize(c), c = r0 x r1
        float t2 = g2x*f.v3x + g2y*f.v3y + g2z*f.v3z;
        float invnc = 1.0f/f.nc;
        float gcx = (g2x - t2*f.v3x)*invnc;
        float gcy = (g2y - t2*f.v3y)*invnc;
        float gcz = (g2z - t2*f.v3z)*invnc;
        // dr0 += r1 x gc ; dr1 += gc x r0
        dr0x += f.r1y*gcz - f.r1z*gcy;
        dr0y += f.r1z*gcx - f.r1x*gcz;
        dr0z += f.r1x*gcy - f.r1y*gcx;
        dr1x += gcy*f.r0z - gcz*f.r0y;
        dr1y += gcz*f.r0x - gcx*f.r0z;
        dr1z += gcx*f.r0y - gcy*f.r0x;

        // r0 = rv0 * inv0
        float dd0 = (dr0x*f.rv0x + dr0y*f.rv0y + dr0z*f.rv0z) * (-f.inv0*f.inv0);
        float c0 = dd0 / f.d0;
        float gt0x = dr0x*f.inv0 + c0*f.rv0x;
        float gt0y = dr0y*f.inv0 + c0*f.rv0y;
        float gt0z = dr0z*f.inv0 + c0*f.rv0z;
        atomicAdd(&gradb[3*f.j0+0], -gt0x);
        atomicAdd(&gradb[3*f.j0+1], -gt0y);
        atomicAdd(&gradb[3*f.j0+2], -gt0z);

        float dd1 = (dr1x*f.rv1x + dr1y*f.rv1y + dr1z*f.rv1z) * (-f.inv1*f.inv1);
        float c1 = dd1 / f.d1;
        float gt1x = dr1x*f.inv1 + c1*f.rv1x;
        float gt1y = dr1y*f.inv1 + c1*f.rv1y;
        float gt1z = dr1z*f.inv1 + c1*f.rv1z;
        atomicAdd(&gradb[3*f.j1+0], -gt1x);
        atomicAdd(&gradb[3*f.j1+1], -gt1y);
        atomicAdd(&gradb[3*f.j1+2], -gt1z);

        atomicAdd(&gradb[3*i+0], gi[0] + gt0x + gt1x);
        atomicAdd(&gradb[3*i+1], gi[1] + gt0y + gt1y);
        atomicAdd(&gradb[3*i+2], gi[2] + gt0z + gt1z);
    }
}

// ---------------------------------------------------------------------------
// Output kernels
// ---------------------------------------------------------------------------
__global__ void zero_kernel(){
    int idx = blockIdx.x*blockDim.x + threadIdx.x;
    if (idx < NATOMS*3) g_grad[idx] = 0.0f;
}

__global__ void energy_kernel(float* __restrict__ out){
    __shared__ float red[256];
    int b = blockIdx.x, tid = threadIdx.x;
    float acc = 0.0f;
    for (int i2 = tid; i2 < NA; i2 += 256) acc += g_e[b*NA + i2];
    red[tid] = acc;
    __syncthreads();
    for (int off = 128; off > 0; off >>= 1){
        if (tid < off) red[tid] += red[tid + off];
        __syncthreads();
    }
    if (tid == 0) out[b] = red[0];
}

__global__ void force_kernel(float* __restrict__ out){
    int idx = blockIdx.x*blockDim.x + threadIdx.x;
    if (idx < NATOMS*3) out[2 + idx] = -g_grad[idx];
}

// ---------------------------------------------------------------------------
extern "C" void kernel_launch(void* const* d_in, const int* in_sizes, int n_in,
                              void* d_out, int out_size){
    const float* xyz   = (const float*)d_in[0];
    const int*   types = (const int*)  d_in[1];
    // d_in[2] = box_size (constant 27 by construction; hardcoded as BOXF)
    const float* W00=(const float*)d_in[3],  *b00=(const float*)d_in[4];
    const float* W01=(const float*)d_in[5],  *b01=(const float*)d_in[6];
    const float* W02=(const float*)d_in[7],  *b02=(const float*)d_in[8];
    const float* W10=(const float*)d_in[9],  *b10=(const float*)d_in[10];
    const float* W11=(const float*)d_in[11], *b11=(const float*)d_in[12];
    const float* W12=(const float*)d_in[13], *b12=(const float*)d_in[14];
    float* out = (float*)d_out;

    zero_kernel<<<(NATOMS*3 + 255)/256, 256>>>();
    knn_kernel<<<NATOMS, 256>>>(xyz, types);
    desc_kernel<<<NATOMS, 64>>>(xyz);
    mlp_kernel<<<NATOMS, HID>>>(types, W00,b00,W01,b01,W02,b02,
                                        W10,b10,W11,b11,W12,b12);
    bwd_kernel<<<NATOMS, 64>>>(xyz);
    energy_kernel<<<BB, 256>>>(out);
    force_kernel<<<(NATOMS*3 + 255)/256, 256>>>(out);
}

// round 3
// speedup vs baseline: 4.4599x; 4.4599x over previous
#include <cuda_runtime.h>
#include <math.h>

#define BB 2
#define NA 2048
#define NATOMS (BB*NA)
#define BOXF 27.0f
#define SEL0 46
#define SEL1 92
#define ASEL0 16
#define ASEL1 32
#define NANG (ASEL0+ASEL1)      /* 48  */
#define NRAD (SEL0+SEL1)        /* 138 */
#define DDIM (NRAD + 3*NANG)    /* 282 */
#define HID 64
#define EPSF 1e-16f

#define NBIN 512
#define BIN_SCALE 37.5f   /* 512 bins over ~[0, 13.65] */
#define CAP0 128
#define CAP1 256

__device__ float g_dist0[NATOMS*SEL0];
__device__ int   g_idx0 [NATOMS*SEL0];
__device__ float g_dist1[NATOMS*SEL1];
__device__ int   g_idx1 [NATOMS*SEL1];
__device__ float g_desc [NATOMS*DDIM];
__device__ float g_gdesc[NATOMS*DDIM];
__device__ float g_grad [NATOMS*3];
__device__ float g_e    [NATOMS];

__device__ __forceinline__ float mic(float d){
    return d - BOXF * rintf(d * (1.0f/BOXF));
}
__device__ __forceinline__ int dbin(float d){
    int b = (int)(d * BIN_SCALE);
    return b > (NBIN-1) ? (NBIN-1) : b;
}

// ---------------------------------------------------------------------------
// K1: per-atom sorted neighbor lists via histogram-select + small bitonic sort
// ---------------------------------------------------------------------------
__global__ void knn_kernel(const float* __restrict__ xyz, const int* __restrict__ types){
    __shared__ float sdist[NA];
    __shared__ unsigned char stype[NA];
    __shared__ int hist[2*NBIN];
    __shared__ unsigned long long cand0[CAP0];
    __shared__ unsigned long long cand1[CAP1];
    __shared__ int cnt0, cnt1, thr0, thr1;

    int atom = blockIdx.x;
    int b = atom >> 11, i = atom & (NA-1);
    const float* xb = xyz + (size_t)b*NA*3;
    float xi = xb[3*i+0], yi = xb[3*i+1], zi = xb[3*i+2];
    int tid = threadIdx.x;

    for (int h = tid; h < 2*NBIN; h += 256) hist[h] = 0;
    if (tid == 0){ cnt0 = 0; cnt1 = 0; }

    for (int j = tid; j < NA; j += 256){
        float dx = mic(xi - xb[3*j+0] + EPSF);
        float dy = mic(yi - xb[3*j+1] + EPSF);
        float dz = mic(zi - xb[3*j+2] + EPSF);
        float d = sqrtf(dx*dx + dy*dy + dz*dz);
        sdist[j] = d;
        stype[j] = (j == i) ? 3 : (unsigned char)types[b*NA + j];
    }
    __syncthreads();

    for (int j = tid; j < NA; j += 256){
        int t = stype[j];
        if (t < 2) atomicAdd(&hist[t*NBIN + dbin(sdist[j])], 1);
    }
    __syncthreads();

    if (tid < 2){
        int k = tid ? SEL1 : SEL0;
        int c = 0, bb2 = 0;
        for (; bb2 < NBIN; bb2++){
            c += hist[tid*NBIN + bb2];
            if (c >= k) break;
        }
        if (tid) thr1 = bb2; else thr0 = bb2;
    }
    __syncthreads();
    int t0 = thr0, t1 = thr1;

    for (int j = tid; j < NA; j += 256){
        int t = stype[j];
        if (t < 2){
            float d = sdist[j];
            int bn = dbin(d);
            unsigned long long key = ((unsigned long long)__float_as_uint(d) << 11)
                                   | (unsigned long long)j;
            if (t == 0){
                if (bn <= t0){
                    int pos = atomicAdd(&cnt0, 1);
                    if (pos < CAP0) cand0[pos] = key;
                }
            } else {
                if (bn <= t1){
                    int pos = atomicAdd(&cnt1, 1);
                    if (pos < CAP1) cand1[pos] = key;
                }
            }
        }
    }
    __syncthreads();
    int c0 = cnt0, c1 = cnt1;
    if (tid < CAP0 && tid >= c0) cand0[tid] = 0xFFFFFFFFFFFFFFFFULL;
    if (tid < CAP1 && tid >= c1) cand1[tid] = 0xFFFFFFFFFFFFFFFFULL;
    __syncthreads();

    // bitonic sort: cand1 over 256, cand0 over 128 piggybacked on same barriers
    for (int k = 2; k <= CAP1; k <<= 1){
        for (int j = k >> 1; j > 0; j >>= 1){
            int m = tid;
            int l = m ^ j;
            if (l > m){
                unsigned long long a = cand1[m], c = cand1[l];
                bool swap = ((m & k) == 0) ? (a > c) : (a < c);
                if (swap){ cand1[m] = c; cand1[l] = a; }
                if (k <= CAP0 && l < CAP0){
                    unsigned long long a0 = cand0[m], c02 = cand0[l];
                    bool sw0 = ((m & k) == 0) ? (a0 > c02) : (a0 < c02);
                    if (sw0){ cand0[m] = c02; cand0[l] = a0; }
                }
            }
            __syncthreads();
        }
    }

    for (int m = tid; m < SEL0; m += 256){
        unsigned long long k64 = cand0[m];
        g_dist0[(size_t)atom*SEL0 + m] = __uint_as_float((unsigned)(k64 >> 11));
        g_idx0 [(size_t)atom*SEL0 + m] = (int)(k64 & 2047ULL);
    }
    for (int m = tid; m < SEL1; m += 256){
        unsigned long long k64 = cand1[m];
        g_dist1[(size_t)atom*SEL1 + m] = __uint_as_float((unsigned)(k64 >> 11));
        g_idx1 [(size_t)atom*SEL1 + m] = (int)(k64 & 2047ULL);
    }
}

// ---------------------------------------------------------------------------
// Local frame (shared by desc forward and backward)
// ---------------------------------------------------------------------------
struct Frame {
    float r0x,r0y,r0z, r1x,r1y,r1z;
    float rv0x,rv0y,rv0z, rv1x,rv1y,rv1z;
    float d0, d1, inv0, inv1;
    float s, np, nc;
    float v2x,v2y,v2z, v3x,v3y,v3z;
    int j0, j1;
};

__device__ Frame make_frame(int atom, const float* xb, float xi, float yi, float zi){
    Frame f;
    float s00 = g_dist0[(size_t)atom*SEL0+0], s01 = g_dist0[(size_t)atom*SEL0+1];
    float s10 = g_dist1[(size_t)atom*SEL1+0], s11 = g_dist1[(size_t)atom*SEL1+1];
    int   i00 = g_idx0 [(size_t)atom*SEL0+0], i01 = g_idx0 [(size_t)atom*SEL0+1];
    int   i10 = g_idx1 [(size_t)atom*SEL1+0], i11 = g_idx1 [(size_t)atom*SEL1+1];
    if (s10 < s00){ f.d0 = s10; f.j0 = i10; } else { f.d0 = s00; f.j0 = i00; }
    if (s11 < s01){ f.d1 = s11; f.j1 = i11; } else { f.d1 = s01; f.j1 = i01; }

    f.rv0x = mic(xi - xb[3*f.j0+0] + EPSF);
    f.rv0y = mic(yi - xb[3*f.j0+1] + EPSF);
    f.rv0z = mic(zi - xb[3*f.j0+2] + EPSF);
    f.rv1x = mic(xi - xb[3*f.j1+0] + EPSF);
    f.rv1y = mic(yi - xb[3*f.j1+1] + EPSF);
    f.rv1z = mic(zi - xb[3*f.j1+2] + EPSF);

    f.inv0 = 1.0f/(f.d0 + EPSF);
    f.inv1 = 1.0f/(f.d1 + EPSF);
    f.r0x = f.rv0x*f.inv0; f.r0y = f.rv0y*f.inv0; f.r0z = f.rv0z*f.inv0;
    f.r1x = f.rv1x*f.inv1; f.r1y = f.rv1y*f.inv1; f.r1z = f.rv1z*f.inv1;

    f.s = f.r0x*f.r1x + f.r0y*f.r1y + f.r0z*f.r1z;
    float px = f.r1x - f.s*f.r0x;
    float py = f.r1y - f.s*f.r0y;
    float pz = f.r1z - f.s*f.r0z;
    f.np = sqrtf(px*px + py*py + pz*pz);
    float invnp = 1.0f/f.np;
    f.v2x = px*invnp; f.v2y = py*invnp; f.v2z = pz*invnp;

    float cx = f.r0y*f.r1z - f.r0z*f.r1y;
    float cy = f.r0z*f.r1x - f.r0x*f.r1z;
    float cz = f.r0x*f.r1y - f.r0y*f.r1x;
    f.nc = sqrtf(cx*cx + cy*cy + cz*cz);
    float invnc = 1.0f/f.nc;
    f.v3x = cx*invnc; f.v3y = cy*invnc; f.v3z = cz*invnc;
    return f;
}

// ---------------------------------------------------------------------------
// K2: descriptor forward (282 per atom)
// ---------------------------------------------------------------------------
__global__ void desc_kernel(const float* __restrict__ xyz){
    __shared__ float A[9];
    int atom = blockIdx.x;
    int b = atom >> 11, i = atom & (NA-1);
    const float* xb = xyz + (size_t)b*NA*3;
    float xi = xb[3*i+0], yi = xb[3*i+1], zi = xb[3*i+2];
    int tid = threadIdx.x;

    if (tid == 0){
        Frame f = make_frame(atom, xb, xi, yi, zi);
        A[0]=f.r0x; A[1]=f.r0y; A[2]=f.r0z;
        A[3]=f.v2x; A[4]=f.v2y; A[5]=f.v2z;
        A[6]=f.v3x; A[7]=f.v3y; A[8]=f.v3z;
    }
    __syncthreads();

    float* dsc = g_desc + (size_t)atom*DDIM;
    for (int m = tid; m < NRAD; m += blockDim.x){
        float s = (m < SEL0) ? g_dist0[(size_t)atom*SEL0 + m]
                             : g_dist1[(size_t)atom*SEL1 + (m - SEL0)];
        dsc[m] = 1.0f/(s + EPSF);
    }
    for (int k = tid; k < NANG; k += blockDim.x){
        int j; float d;
        if (k < ASEL0){ j = g_idx0[(size_t)atom*SEL0 + k]; d = g_dist0[(size_t)atom*SEL0 + k]; }
        else          { j = g_idx1[(size_t)atom*SEL1 + (k-ASEL0)]; d = g_dist1[(size_t)atom*SEL1 + (k-ASEL0)]; }
        float rx = mic(xi - xb[3*j+0] + EPSF);
        float ry = mic(yi - xb[3*j+1] + EPSF);
        float rz = mic(zi - xb[3*j+2] + EPSF);
        float inv = 1.0f/(d + EPSF);
        float w = inv*inv;
        dsc[NRAD + 3*k + 0] = (A[0]*rx + A[1]*ry + A[2]*rz)*w;
        dsc[NRAD + 3*k + 1] = (A[3]*rx + A[4]*ry + A[5]*rz)*w;
        dsc[NRAD + 3*k + 2] = (A[6]*rx + A[7]*ry + A[8]*rz)*w;
    }
}

// ---------------------------------------------------------------------------
// K3: MLP forward + backward, 8 atoms per block, 64 threads (thread = column)
// ---------------------------------------------------------------------------
#define TM 8
#define SD_PITCH 9
#define HP 65

__global__ void mlp_kernel(const int* __restrict__ types,
    const float* __restrict__ W00, const float* __restrict__ b00,
    const float* __restrict__ W01, const float* __restrict__ b01,
    const float* __restrict__ W02, const float* __restrict__ b02,
    const float* __restrict__ W10, const float* __restrict__ b10,
    const float* __restrict__ W11, const float* __restrict__ b11,
    const float* __restrict__ W12, const float* __restrict__ b12){

    __shared__ int   ord[TM];
    __shared__ int   sc0;
    __shared__ float sdT[DDIM*SD_PITCH];
    __shared__ float h1s[TM*HP];
    __shared__ float gh2s[TM*HP];
    __shared__ float gz1s[TM*HP];
    __shared__ float red[TM*HP];

    int tid = threadIdx.x;
    int base = blockIdx.x * TM;

    if (tid == 0){
        int c = 0;
        for (int p = 0; p < TM; p++) if (types[base+p] == 0) ord[c++] = base+p;
        sc0 = c;
        for (int p = 0; p < TM; p++) if (types[base+p] != 0) ord[c++] = base+p;
    }
    __syncthreads();
    int c0 = sc0;

    for (int d = tid; d < DDIM; d += HID){
        #pragma unroll
        for (int p = 0; p < TM; p++)
            sdT[d*SD_PITCH + p] = g_desc[(size_t)ord[p]*DDIM + d];
    }
    __syncthreads();

    bool pr[TM];
    #pragma unroll
    for (int p = 0; p < TM; p++) pr[p] = (p < c0);

    // ---- layer 1 ----
    float acc[TM];
    {
        float bz0 = b00[tid], bz1 = b10[tid];
        #pragma unroll
        for (int p = 0; p < TM; p++) acc[p] = pr[p] ? bz0 : bz1;
    }
    for (int d = 0; d < DDIM; d++){
        float w0 = W00[d*HID + tid];
        float w1 = W10[d*HID + tid];
        #pragma unroll
        for (int p = 0; p < TM; p++){
            float x = sdT[d*SD_PITCH + p];
            acc[p] = fmaf(x, pr[p] ? w0 : w1, acc[p]);
        }
    }
    float h1[TM];
    #pragma unroll
    for (int p = 0; p < TM; p++){
        h1[p] = tanhf(acc[p]);
        h1s[p*HP + tid] = h1[p];
    }
    __syncthreads();

    // ---- layer 2 ----
    {
        float bz0 = b01[tid], bz1 = b11[tid];
        #pragma unroll
        for (int p = 0; p < TM; p++) acc[p] = pr[p] ? bz0 : bz1;
    }
    for (int s = 0; s < HID; s++){
        float w0 = W01[s*HID + tid];
        float w1 = W11[s*HID + tid];
        #pragma unroll
        for (int p = 0; p < TM; p++){
            float x = h1s[p*HP + s];
            acc[p] = fmaf(x, pr[p] ? w0 : w1, acc[p]);
        }
    }
    float h2[TM], w2sel[TM];
    {
        float w20 = W02[tid], w21 = W12[tid];
        #pragma unroll
        for (int p = 0; p < TM; p++){
            h2[p] = tanhf(acc[p]);
            w2sel[p] = pr[p] ? w20 : w21;
            red[p*HP + tid] = h2[p] * w2sel[p];
        }
    }
    __syncthreads();
    for (int off = HID/2; off > 0; off >>= 1){
        if (tid < off){
            #pragma unroll
            for (int p = 0; p < TM; p++)
                red[p*HP + tid] += red[p*HP + tid + off];
        }
        __syncthreads();
    }
    if (tid == 0){
        float bb0 = b02[0], bb1 = b12[0];
        #pragma unroll
        for (int p = 0; p < TM; p++)
            g_e[ord[p]] = red[p*HP] + (pr[p] ? bb0 : bb1);
    }

    // ---- backward ----
    #pragma unroll
    for (int p = 0; p < TM; p++)
        gh2s[p*HP + tid] = w2sel[p] * (1.0f - h2[p]*h2[p]);
    __syncthreads();

    #pragma unroll
    for (int p = 0; p < TM; p++) acc[p] = 0.0f;
    for (int s = 0; s < HID; s++){
        float w0 = W01[tid*HID + s];
        float w1 = W11[tid*HID + s];
        #pragma unroll
        for (int p = 0; p < TM; p++){
            float x = gh2s[p*HP + s];
            acc[p] = fmaf(x, pr[p] ? w0 : w1, acc[p]);
        }
    }
    #pragma unroll
    for (int p = 0; p < TM; p++)
        gz1s[p*HP + tid] = acc[p] * (1.0f - h1[p]*h1[p]);
    __syncthreads();

    for (int d = tid; d < DDIM; d += HID){
        float ag[TM];
        #pragma unroll
        for (int p = 0; p < TM; p++) ag[p] = 0.0f;
        for (int s = 0; s < HID; s++){
            float w0 = W00[d*HID + s];
            float w1 = W10[d*HID + s];
            #pragma unroll
            for (int p = 0; p < TM; p++){
                float x = gz1s[p*HP + s];
                ag[p] = fmaf(x, pr[p] ? w0 : w1, ag[p]);
            }
        }
        #pragma unroll
        for (int p = 0; p < TM; p++)
            g_gdesc[(size_t)ord[p]*DDIM + d] = ag[p];
    }
}

// ---------------------------------------------------------------------------
// K4: backward through descriptors -> position gradients (atomic scatter)
// ---------------------------------------------------------------------------
__global__ void bwd_kernel(const float* __restrict__ xyz){
    __shared__ float A[9];
    __shared__ float G[9];
    __shared__ float gi[3];
    int atom = blockIdx.x;
    int b = atom >> 11, i = atom & (NA-1);
    const float* xb = xyz + (size_t)b*NA*3;
    float xi = xb[3*i+0], yi = xb[3*i+1], zi = xb[3*i+2];
    int tid = threadIdx.x;

    Frame f;
    if (tid == 0){
        f = make_frame(atom, xb, xi, yi, zi);
        A[0]=f.r0x; A[1]=f.r0y; A[2]=f.r0z;
        A[3]=f.v2x; A[4]=f.v2y; A[5]=f.v2z;
        A[6]=f.v3x; A[7]=f.v3y; A[8]=f.v3z;
    }
    if (tid < 9) G[tid] = 0.0f;
    if (tid < 3) gi[tid] = 0.0f;
    __syncthreads();

    const float* gd = g_gdesc + (size_t)atom*DDIM;
    float* gradb = g_grad + (size_t)b*NA*3;

    if (tid < NANG){
        int k = tid;
        int j; float dN;
        if (k < ASEL0){ j = g_idx0[(size_t)atom*SEL0 + k]; dN = g_dist0[(size_t)atom*SEL0 + k]; }
        else          { j = g_idx1[(size_t)atom*SEL1 + (k-ASEL0)]; dN = g_dist1[(size_t)atom*SEL1 + (k-ASEL0)]; }
        float rx = mic(xi - xb[3*j+0] + EPSF);
        float ry = mic(yi - xb[3*j+1] + EPSF);
        float rz = mic(zi - xb[3*j+2] + EPSF);
        float gx = gd[NRAD + 3*k + 0];
        float gy = gd[NRAD + 3*k + 1];
        float gz3= gd[NRAD + 3*k + 2];
        float inv = 1.0f/(dN + EPSF);
        float w = inv*inv;
        float Arx = A[0]*rx + A[1]*ry + A[2]*rz;
        float Ary = A[3]*rx + A[4]*ry + A[5]*rz;
        float Arz = A[6]*rx + A[7]*ry + A[8]*rz;
        float gvx = (A[0]*gx + A[3]*gy + A[6]*gz3)*w;
        float gvy = (A[1]*gx + A[4]*gy + A[7]*gz3)*w;
        float gvz = (A[2]*gx + A[5]*gy + A[8]*gz3)*w;
        float gdd = (gx*Arx + gy*Ary + gz3*Arz) * (-2.0f*w*inv);
        atomicAdd(&G[0], w*gx*rx);  atomicAdd(&G[1], w*gx*ry);  atomicAdd(&G[2], w*gx*rz);
        atomicAdd(&G[3], w*gy*rx);  atomicAdd(&G[4], w*gy*ry);  atomicAdd(&G[5], w*gy*rz);
        atomicAdd(&G[6], w*gz3*rx); atomicAdd(&G[7], w*gz3*ry); atomicAdd(&G[8], w*gz3*rz);
        float cf = gdd / dN;
        float gtx = gvx + cf*rx, gty = gvy + cf*ry, gtz = gvz + cf*rz;
        atomicAdd(&gi[0], gtx); atomicAdd(&gi[1], gty); atomicAdd(&gi[2], gtz);
        atomicAdd(&gradb[3*j+0], -gtx);
        atomicAdd(&gradb[3*j+1], -gty);
        atomicAdd(&gradb[3*j+2], -gtz);
    }

    for (int m = tid; m < NRAD; m += blockDim.x){
        int j; float s;
        if (m < SEL0){ j = g_idx0[(size_t)atom*SEL0 + m]; s = g_dist0[(size_t)atom*SEL0 + m]; }
        else         { j = g_idx1[(size_t)atom*SEL1 + (m-SEL0)]; s = g_dist1[(size_t)atom*SEL1 + (m-SEL0)]; }
        float gR = gd[m];
        float invr = 1.0f/(s + EPSF);
        float cf = -gR*invr*invr / s;
        float rx = mic(xi - xb[3*j+0] + EPSF);
        float ry = mic(yi - xb[3*j+1] + EPSF);
        float rz = mic(zi - xb[3*j+2] + EPSF);
        float gtx = cf*rx, gty = cf*ry, gtz = cf*rz;
        atomicAdd(&gi[0], gtx); atomicAdd(&gi[1], gty); atomicAdd(&gi[2], gtz);
        atomicAdd(&gradb[3*j+0], -gtx);
        atomicAdd(&gradb[3*j+1], -gty);
        atomicAdd(&gradb[3*j+2], -gtz);
    }
    __syncthreads();

    if (tid == 0){
        float g0x=G[0], g0y=G[1], g0z=G[2];
        float g1x=G[3], g1y=G[4], g1z=G[5];
        float g2x=G[6], g2y=G[7], g2z=G[8];

        float dr0x = g0x, dr0y = g0y, dr0z = g0z;
        float dr1x = 0.f, dr1y = 0.f, dr1z = 0.f;

        float t1 = g1x*f.v2x + g1y*f.v2y + g1z*f.v2z;
        float invnp = 1.0f/f.np;
        float gpx = (g1x - t1*f.v2x)*invnp;
        float gpy = (g1y - t1*f.v2y)*invnp;
        float gpz = (g1z - t1*f.v2z)*invnp;
        float gpr0 = gpx*f.r0x + gpy*f.r0y + gpz*f.r0z;
        dr1x += gpx - gpr0*f.r0x;
        dr1y += gpy - gpr0*f.r0y;
        dr1z += gpz - gpr0*f.r0z;
        dr0x += -f.s*gpx - gpr0*f.r1x;
        dr0y += -f.s*gpy - gpr0*f.r1y;
        dr0z += -f.s*gpz - gpr0*f.r1z;

        float t2 = g2x*f.v3x + g2y*f.v3y + g2z*f.v3z;
        float invnc = 1.0f/f.nc;
        float gcx = (g2x - t2*f.v3x)*invnc;
        float gcy = (g2y - t2*f.v3y)*invnc;
        float gcz = (g2z - t2*f.v3z)*invnc;
        dr0x += f.r1y*gcz - f.r1z*gcy;
        dr0y += f.r1z*gcx - f.r1x*gcz;
        dr0z += f.r1x*gcy - f.r1y*gcx;
        dr1x += gcy*f.r0z - gcz*f.r0y;
        dr1y += gcz*f.r0x - gcx*f.r0z;
        dr1z += gcx*f.r0y - gcy*f.r0x;

        float dd0 = (dr0x*f.rv0x + dr0y*f.rv0y + dr0z*f.rv0z) * (-f.inv0*f.inv0);
        float c0 = dd0 / f.d0;
        float gt0x = dr0x*f.inv0 + c0*f.rv0x;
        float gt0y = dr0y*f.inv0 + c0*f.rv0y;
        float gt0z = dr0z*f.inv0 + c0*f.rv0z;
        atomicAdd(&gradb[3*f.j0+0], -gt0x);
        atomicAdd(&gradb[3*f.j0+1], -gt0y);
        atomicAdd(&gradb[3*f.j0+2], -gt0z);

        float dd1 = (dr1x*f.rv1x + dr1y*f.rv1y + dr1z*f.rv1z) * (-f.inv1*f.inv1);
        float c1 = dd1 / f.d1;
        float gt1x = dr1x*f.inv1 + c1*f.rv1x;
        float gt1y = dr1y*f.inv1 + c1*f.rv1y;
        float gt1z = dr1z*f.inv1 + c1*f.rv1z;
        atomicAdd(&gradb[3*f.j1+0], -gt1x);
        atomicAdd(&gradb[3*f.j1+1], -gt1y);
        atomicAdd(&gradb[3*f.j1+2], -gt1z);

        atomicAdd(&gradb[3*i+0], gi[0] + gt0x + gt1x);
        atomicAdd(&gradb[3*i+1], gi[1] + gt0y + gt1y);
        atomicAdd(&gradb[3*i+2], gi[2] + gt0z + gt1z);
    }
}

// ---------------------------------------------------------------------------
// Output kernels
// ---------------------------------------------------------------------------
__global__ void zero_kernel(){
    int idx = blockIdx.x*blockDim.x + threadIdx.x;
    if (idx < NATOMS*3) g_grad[idx] = 0.0f;
}

__global__ void energy_kernel(float* __restrict__ out){
    __shared__ float red[256];
    int b = blockIdx.x, tid = threadIdx.x;
    float acc = 0.0f;
    for (int i2 = tid; i2 < NA; i2 += 256) acc += g_e[b*NA + i2];
    red[tid] = acc;
    __syncthreads();
    for (int off = 128; off > 0; off >>= 1){
        if (tid < off) red[tid] += red[tid + off];
        __syncthreads();
    }
    if (tid == 0) out[b] = red[0];
}

__global__ void force_kernel(float* __restrict__ out){
    int idx = blockIdx.x*blockDim.x + threadIdx.x;
    if (idx < NATOMS*3) out[2 + idx] = -g_grad[idx];
}

// ---------------------------------------------------------------------------
extern "C" void kernel_launch(void* const* d_in, const int* in_sizes, int n_in,
                              void* d_out, int out_size){
    const float* xyz   = (const float*)d_in[0];
    const int*   types = (const int*)  d_in[1];
    const float* W00=(const float*)d_in[3],  *b00=(const float*)d_in[4];
    const float* W01=(const float*)d_in[5],  *b01=(const float*)d_in[6];
    const float* W02=(const float*)d_in[7],  *b02=(const float*)d_in[8];
    const float* W10=(const float*)d_in[9],  *b10=(const float*)d_in[10];
    const float* W11=(const float*)d_in[11], *b11=(const float*)d_in[12];
    const float* W12=(const float*)d_in[13], *b12=(const float*)d_in[14];
    float* out = (float*)d_out;

    zero_kernel<<<(NATOMS*3 + 255)/256, 256>>>();
    knn_kernel<<<NATOMS, 256>>>(xyz, types);
    desc_kernel<<<NATOMS, 64>>>(xyz);
    mlp_kernel<<<NATOMS/TM, HID>>>(types, W00,b00,W01,b01,W02,b02,
                                           W10,b10,W11,b11,W12,b12);
    bwd_kernel<<<NATOMS, 64>>>(xyz);
    energy_kernel<<<BB, 256>>>(out);
    force_kernel<<<(NATOMS*3 + 255)/256, 256>>>(out);
}

// round 4
// speedup vs baseline: 6.1918x; 1.3883x over previous
#include <cuda_runtime.h>
#include <math.h>

#define BB 2
#define NA 2048
#define NATOMS (BB*NA)
#define BOXF 27.0f
#define SEL0 46
#define SEL1 92
#define ASEL0 16
#define ASEL1 32
#define NANG (ASEL0+ASEL1)      /* 48  */
#define NRAD (SEL0+SEL1)        /* 138 */
#define DDIM (NRAD + 3*NANG)    /* 282 */
#define HID 64
#define EPSF 1e-16f

#define NBIN 512
#define BIN_SCALE 37.5f
#define CAP0 128
#define CAP1 256

__device__ float g_dist0[NATOMS*SEL0];
__device__ int   g_idx0 [NATOMS*SEL0];
__device__ float g_dist1[NATOMS*SEL1];
__device__ int   g_idx1 [NATOMS*SEL1];
__device__ float g_desc [NATOMS*DDIM];
__device__ float g_gdesc[NATOMS*DDIM];
__device__ float g_grad [NATOMS*3];
__device__ float g_e    [NATOMS];
__device__ float g_h1   [NATOMS*HID];
__device__ float g_gh2  [NATOMS*HID];
__device__ float g_gz1  [NATOMS*HID];
__device__ float g_W0T  [2*HID*DDIM];   /* [type][s][d] = W0[type][d][s] */
__device__ float g_W1T  [2*HID*HID];    /* [type][s][c] = W1[type][c][s] */

__device__ __forceinline__ float mic(float d){
    return d - BOXF * rintf(d * (1.0f/BOXF));
}
__device__ __forceinline__ int dbin(float d){
    int b = (int)(d * BIN_SCALE);
    return b > (NBIN-1) ? (NBIN-1) : b;
}

// ---------------------------------------------------------------------------
// K1: per-atom sorted neighbor lists via histogram-select + small bitonic sort
// ---------------------------------------------------------------------------
__global__ void knn_kernel(const float* __restrict__ xyz, const int* __restrict__ types){
    __shared__ float sdist[NA];
    __shared__ unsigned char stype[NA];
    __shared__ int hist[2*NBIN];
    __shared__ unsigned long long cand0[CAP0];
    __shared__ unsigned long long cand1[CAP1];
    __shared__ int cnt0, cnt1, thr0, thr1;

    int atom = blockIdx.x;
    int b = atom >> 11, i = atom & (NA-1);
    const float* xb = xyz + (size_t)b*NA*3;
    float xi = xb[3*i+0], yi = xb[3*i+1], zi = xb[3*i+2];
    int tid = threadIdx.x;

    for (int h = tid; h < 2*NBIN; h += 256) hist[h] = 0;
    if (tid == 0){ cnt0 = 0; cnt1 = 0; }

    for (int j = tid; j < NA; j += 256){
        float dx = mic(xi - xb[3*j+0] + EPSF);
        float dy = mic(yi - xb[3*j+1] + EPSF);
        float dz = mic(zi - xb[3*j+2] + EPSF);
        float d = sqrtf(dx*dx + dy*dy + dz*dz);
        sdist[j] = d;
        stype[j] = (j == i) ? 3 : (unsigned char)types[b*NA + j];
    }
    __syncthreads();

    for (int j = tid; j < NA; j += 256){
        int t = stype[j];
        if (t < 2) atomicAdd(&hist[t*NBIN + dbin(sdist[j])], 1);
    }
    __syncthreads();

    if (tid < 2){
        int k = tid ? SEL1 : SEL0;
        int c = 0, bb2 = 0;
        for (; bb2 < NBIN; bb2++){
            c += hist[tid*NBIN + bb2];
            if (c >= k) break;
        }
        if (tid) thr1 = bb2; else thr0 = bb2;
    }
    __syncthreads();
    int t0 = thr0, t1 = thr1;

    for (int j = tid; j < NA; j += 256){
        int t = stype[j];
        if (t < 2){
            float d = sdist[j];
            int bn = dbin(d);
            unsigned long long key = ((unsigned long long)__float_as_uint(d) << 11)
                                   | (unsigned long long)j;
            if (t == 0){
                if (bn <= t0){
                    int pos = atomicAdd(&cnt0, 1);
                    if (pos < CAP0) cand0[pos] = key;
                }
            } else {
                if (bn <= t1){
                    int pos = atomicAdd(&cnt1, 1);
                    if (pos < CAP1) cand1[pos] = key;
                }
            }
        }
    }
    __syncthreads();
    int c0 = cnt0, c1 = cnt1;
    if (tid < CAP0 && tid >= c0) cand0[tid] = 0xFFFFFFFFFFFFFFFFULL;
    if (tid < CAP1 && tid >= c1) cand1[tid] = 0xFFFFFFFFFFFFFFFFULL;
    __syncthreads();

    for (int k = 2; k <= CAP1; k <<= 1){
        for (int j = k >> 1; j > 0; j >>= 1){
            int m = tid;
            int l = m ^ j;
            if (l > m){
                unsigned long long a = cand1[m], c = cand1[l];
                bool swap = ((m & k) == 0) ? (a > c) : (a < c);
                if (swap){ cand1[m] = c; cand1[l] = a; }
                if (k <= CAP0 && l < CAP0){
                    unsigned long long a0 = cand0[m], c02 = cand0[l];
                    bool sw0 = ((m & k) == 0) ? (a0 > c02) : (a0 < c02);
                    if (sw0){ cand0[m] = c02; cand0[l] = a0; }
                }
            }
            __syncthreads();
        }
    }

    for (int m = tid; m < SEL0; m += 256){
        unsigned long long k64 = cand0[m];
        g_dist0[(size_t)atom*SEL0 + m] = __uint_as_float((unsigned)(k64 >> 11));
        g_idx0 [(size_t)atom*SEL0 + m] = (int)(k64 & 2047ULL);
    }
    for (int m = tid; m < SEL1; m += 256){
        unsigned long long k64 = cand1[m];
        g_dist1[(size_t)atom*SEL1 + m] = __uint_as_float((unsigned)(k64 >> 11));
        g_idx1 [(size_t)atom*SEL1 + m] = (int)(k64 & 2047ULL);
    }
}

// ---------------------------------------------------------------------------
// Local frame
// ---------------------------------------------------------------------------
struct Frame {
    float r0x,r0y,r0z, r1x,r1y,r1z;
    float rv0x,rv0y,rv0z, rv1x,rv1y,rv1z;
    float d0, d1, inv0, inv1;
    float s, np, nc;
    float v2x,v2y,v2z, v3x,v3y,v3z;
    int j0, j1;
};

__device__ Frame make_frame(int atom, const float* xb, float xi, float yi, float zi){
    Frame f;
    float s00 = g_dist0[(size_t)atom*SEL0+0], s01 = g_dist0[(size_t)atom*SEL0+1];
    float s10 = g_dist1[(size_t)atom*SEL1+0], s11 = g_dist1[(size_t)atom*SEL1+1];
    int   i00 = g_idx0 [(size_t)atom*SEL0+0], i01 = g_idx0 [(size_t)atom*SEL0+1];
    int   i10 = g_idx1 [(size_t)atom*SEL1+0], i11 = g_idx1 [(size_t)atom*SEL1+1];
    if (s10 < s00){ f.d0 = s10; f.j0 = i10; } else { f.d0 = s00; f.j0 = i00; }
    if (s11 < s01){ f.d1 = s11; f.j1 = i11; } else { f.d1 = s01; f.j1 = i01; }

    f.rv0x = mic(xi - xb[3*f.j0+0] + EPSF);
    f.rv0y = mic(yi - xb[3*f.j0+1] + EPSF);
    f.rv0z = mic(zi - xb[3*f.j0+2] + EPSF);
    f.rv1x = mic(xi - xb[3*f.j1+0] + EPSF);
    f.rv1y = mic(yi - xb[3*f.j1+1] + EPSF);
    f.rv1z = mic(zi - xb[3*f.j1+2] + EPSF);

    f.inv0 = 1.0f/(f.d0 + EPSF);
    f.inv1 = 1.0f/(f.d1 + EPSF);
    f.r0x = f.rv0x*f.inv0; f.r0y = f.rv0y*f.inv0; f.r0z = f.rv0z*f.inv0;
    f.r1x = f.rv1x*f.inv1; f.r1y = f.rv1y*f.inv1; f.r1z = f.rv1z*f.inv1;

    f.s = f.r0x*f.r1x + f.r0y*f.r1y + f.r0z*f.r1z;
    float px = f.r1x - f.s*f.r0x;
    float py = f.r1y - f.s*f.r0y;
    float pz = f.r1z - f.s*f.r0z;
    f.np = sqrtf(px*px + py*py + pz*pz);
    float invnp = 1.0f/f.np;
    f.v2x = px*invnp; f.v2y = py*invnp; f.v2z = pz*invnp;

    float cx = f.r0y*f.r1z - f.r0z*f.r1y;
    float cy = f.r0z*f.r1x - f.r0x*f.r1z;
    float cz = f.r0x*f.r1y - f.r0y*f.r1x;
    f.nc = sqrtf(cx*cx + cy*cy + cz*cz);
    float invnc = 1.0f/f.nc;
    f.v3x = cx*invnc; f.v3y = cy*invnc; f.v3z = cz*invnc;
    return f;
}

// ---------------------------------------------------------------------------
// K2: descriptor forward
// ---------------------------------------------------------------------------
__global__ void desc_kernel(const float* __restrict__ xyz){
    __shared__ float A[9];
    int atom = blockIdx.x;
    int b = atom >> 11, i = atom & (NA-1);
    const float* xb = xyz + (size_t)b*NA*3;
    float xi = xb[3*i+0], yi = xb[3*i+1], zi = xb[3*i+2];
    int tid = threadIdx.x;

    if (tid == 0){
        Frame f = make_frame(atom, xb, xi, yi, zi);
        A[0]=f.r0x; A[1]=f.r0y; A[2]=f.r0z;
        A[3]=f.v2x; A[4]=f.v2y; A[5]=f.v2z;
        A[6]=f.v3x; A[7]=f.v3y; A[8]=f.v3z;
    }
    __syncthreads();

    float* dsc = g_desc + (size_t)atom*DDIM;
    for (int m = tid; m < NRAD; m += blockDim.x){
        float s = (m < SEL0) ? g_dist0[(size_t)atom*SEL0 + m]
                             : g_dist1[(size_t)atom*SEL1 + (m - SEL0)];
        dsc[m] = 1.0f/(s + EPSF);
    }
    for (int k = tid; k < NANG; k += blockDim.x){
        int j; float d;
        if (k < ASEL0){ j = g_idx0[(size_t)atom*SEL0 + k]; d = g_dist0[(size_t)atom*SEL0 + k]; }
        else          { j = g_idx1[(size_t)atom*SEL1 + (k-ASEL0)]; d = g_dist1[(size_t)atom*SEL1 + (k-ASEL0)]; }
        float rx = mic(xi - xb[3*j+0] + EPSF);
        float ry = mic(yi - xb[3*j+1] + EPSF);
        float rz = mic(zi - xb[3*j+2] + EPSF);
        float inv = 1.0f/(d + EPSF);
        float w = inv*inv;
        dsc[NRAD + 3*k + 0] = (A[0]*rx + A[1]*ry + A[2]*rz)*w;
        dsc[NRAD + 3*k + 1] = (A[3]*rx + A[4]*ry + A[5]*rz)*w;
        dsc[NRAD + 3*k + 2] = (A[6]*rx + A[7]*ry + A[8]*rz)*w;
    }
}

// ---------------------------------------------------------------------------
// Weight transposes (one-time per launch)
// ---------------------------------------------------------------------------
__global__ void transpose_kernel(
    const float* __restrict__ W00, const float* __restrict__ W10,
    const float* __restrict__ W01, const float* __restrict__ W11){
    int idx = blockIdx.x*blockDim.x + threadIdx.x;
    // W0T[t][s*DDIM+d] = W0t[d*HID+s] : 2*282*64 = 36096 elems
    if (idx < 2*DDIM*HID){
        int t = idx / (DDIM*HID);
        int r = idx % (DDIM*HID);     // r = d*HID+s (coalesced read)
        int d = r / HID, s = r % HID;
        const float* W = t ? W10 : W00;
        g_W0T[t*HID*DDIM + s*DDIM + d] = W[r];
    }
    // W1T[t][s*HID+c] = W1t[c*HID+s] : 2*64*64 = 8192 elems
    if (idx < 2*HID*HID){
        int t = idx / (HID*HID);
        int r = idx % (HID*HID);      // r = c*HID+s
        int c = r / HID, s = r % HID;
        const float* W = t ? W11 : W01;
        g_W1T[t*HID*HID + s*HID + c] = W[r];
    }
}

// ---------------------------------------------------------------------------
// MLP as 4 thin GEMM-like kernels
// ---------------------------------------------------------------------------
#define AF 4   /* atoms per block in fwd1/fwd2/bwd1 (block = AF*64 threads) */

__global__ void fwd1_kernel(const int* __restrict__ types,
    const float* __restrict__ W00, const float* __restrict__ b00,
    const float* __restrict__ W10, const float* __restrict__ b10){
    __shared__ float sX[AF][DDIM];
    int tid = threadIdx.x;
    int j = tid & (HID-1);
    int a = tid >> 6;
    int atom = blockIdx.x*AF + a;

    for (int d = tid; d < AF*DDIM; d += AF*HID){
        int aa = d / DDIM, dd = d % DDIM;
        sX[aa][dd] = g_desc[(size_t)(blockIdx.x*AF + aa)*DDIM + dd];
    }
    __syncthreads();

    int t = types[atom];
    const float* W = t ? W10 : W00;
    const float* B = t ? b10 : b00;
    float acc = B[j];
    const float* xr = sX[a];
    #pragma unroll 4
    for (int d = 0; d < DDIM; d++)
        acc = fmaf(xr[d], W[d*HID + j], acc);
    g_h1[(size_t)atom*HID + j] = tanhf(acc);
}

__global__ void fwd2_kernel(const int* __restrict__ types,
    const float* __restrict__ W01, const float* __restrict__ b01,
    const float* __restrict__ W11, const float* __restrict__ b11,
    const float* __restrict__ W02, const float* __restrict__ b02,
    const float* __restrict__ W12, const float* __restrict__ b12){
    __shared__ float sH[AF][HID];
    __shared__ float red[AF][HID];
    int tid = threadIdx.x;
    int j = tid & (HID-1);
    int a = tid >> 6;
    int atom = blockIdx.x*AF + a;

    sH[a][j] = g_h1[(size_t)atom*HID + j];
    __syncthreads();

    int t = types[atom];
    const float* W = t ? W11 : W01;
    float acc = t ? b11[j] : b01[j];
    const float* hr = sH[a];
    #pragma unroll 4
    for (int s = 0; s < HID; s++)
        acc = fmaf(hr[s], W[s*HID + j], acc);
    float h2 = tanhf(acc);
    float w2 = t ? W12[j] : W02[j];
    red[a][j] = h2 * w2;
    g_gh2[(size_t)atom*HID + j] = w2 * (1.0f - h2*h2);
    __syncthreads();
    for (int off = HID/2; off > 0; off >>= 1){
        if (j < off) red[a][j] += red[a][j + off];
        __syncthreads();
    }
    if (j == 0) g_e[atom] = red[a][0] + (t ? b12[0] : b02[0]);
}

__global__ void bwd1_kernel(const int* __restrict__ types){
    __shared__ float sG[AF][HID];
    int tid = threadIdx.x;
    int j = tid & (HID-1);
    int a = tid >> 6;
    int atom = blockIdx.x*AF + a;

    sG[a][j] = g_gh2[(size_t)atom*HID + j];
    __syncthreads();

    int t = types[atom];
    const float* W1T = g_W1T + (size_t)t*HID*HID;
    float acc = 0.0f;
    const float* gr = sG[a];
    #pragma unroll 4
    for (int s = 0; s < HID; s++)
        acc = fmaf(gr[s], W1T[s*HID + j], acc);
    float h1 = g_h1[(size_t)atom*HID + j];
    g_gz1[(size_t)atom*HID + j] = acc * (1.0f - h1*h1);
}

__global__ void bwd2_kernel(const int* __restrict__ types){
    long long idx = (long long)blockIdx.x*blockDim.x + threadIdx.x;
    if (idx >= (long long)NATOMS*DDIM) return;
    int atom = (int)(idx / DDIM);
    int d    = (int)(idx % DDIM);
    int t = types[atom];
    const float* W0T = g_W0T + (size_t)t*HID*DDIM;
    const float* gz = g_gz1 + (size_t)atom*HID;
    float acc = 0.0f;
    #pragma unroll 4
    for (int s = 0; s < HID; s++)
        acc = fmaf(gz[s], W0T[s*DDIM + d], acc);
    g_gdesc[idx] = acc;
}

// ---------------------------------------------------------------------------
// K4: backward through descriptors -> position gradients (atomic scatter)
// ---------------------------------------------------------------------------
__global__ void bwd_kernel(const float* __restrict__ xyz){
    __shared__ float A[9];
    __shared__ float G[9];
    __shared__ float gi[3];
    int atom = blockIdx.x;
    int b = atom >> 11, i = atom & (NA-1);
    const float* xb = xyz + (size_t)b*NA*3;
    float xi = xb[3*i+0], yi = xb[3*i+1], zi = xb[3*i+2];
    int tid = threadIdx.x;

    Frame f;
    if (tid == 0){
        f = make_frame(atom, xb, xi, yi, zi);
        A[0]=f.r0x; A[1]=f.r0y; A[2]=f.r0z;
        A[3]=f.v2x; A[4]=f.v2y; A[5]=f.v2z;
        A[6]=f.v3x; A[7]=f.v3y; A[8]=f.v3z;
    }
    if (tid < 9) G[tid] = 0.0f;
    if (tid < 3) gi[tid] = 0.0f;
    __syncthreads();

    const float* gd = g_gdesc + (size_t)atom*DDIM;
    float* gradb = g_grad + (size_t)b*NA*3;

    if (tid < NANG){
        int k = tid;
        int j; float dN;
        if (k < ASEL0){ j = g_idx0[(size_t)atom*SEL0 + k]; dN = g_dist0[(size_t)atom*SEL0 + k]; }
        else          { j = g_idx1[(size_t)atom*SEL1 + (k-ASEL0)]; dN = g_dist1[(size_t)atom*SEL1 + (k-ASEL0)]; }
        float rx = mic(xi - xb[3*j+0] + EPSF);
        float ry = mic(yi - xb[3*j+1] + EPSF);
        float rz = mic(zi - xb[3*j+2] + EPSF);
        float gx = gd[NRAD + 3*k + 0];
        float gy = gd[NRAD + 3*k + 1];
        float gz3= gd[NRAD + 3*k + 2];
        float inv = 1.0f/(dN + EPSF);
        float w = inv*inv;
        float Arx = A[0]*rx + A[1]*ry + A[2]*rz;
        float Ary = A[3]*rx + A[4]*ry + A[5]*rz;
        float Arz = A[6]*rx + A[7]*ry + A[8]*rz;
        float gvx = (A[0]*gx + A[3]*gy + A[6]*gz3)*w;
        float gvy = (A[1]*gx + A[4]*gy + A[7]*gz3)*w;
        float gvz = (A[2]*gx + A[5]*gy + A[8]*gz3)*w;
        float gdd = (gx*Arx + gy*Ary + gz3*Arz) * (-2.0f*w*inv);
        atomicAdd(&G[0], w*gx*rx);  atomicAdd(&G[1], w*gx*ry);  atomicAdd(&G[2], w*gx*rz);
        atomicAdd(&G[3], w*gy*rx);  atomicAdd(&G[4], w*gy*ry);  atomicAdd(&G[5], w*gy*rz);
        atomicAdd(&G[6], w*gz3*rx); atomicAdd(&G[7], w*gz3*ry); atomicAdd(&G[8], w*gz3*rz);
        float cf = gdd / dN;
        float gtx = gvx + cf*rx, gty = gvy + cf*ry, gtz = gvz + cf*rz;
        atomicAdd(&gi[0], gtx); atomicAdd(&gi[1], gty); atomicAdd(&gi[2], gtz);
        atomicAdd(&gradb[3*j+0], -gtx);
        atomicAdd(&gradb[3*j+1], -gty);
        atomicAdd(&gradb[3*j+2], -gtz);
    }

    for (int m = tid; m < NRAD; m += blockDim.x){
        int j; float s;
        if (m < SEL0){ j = g_idx0[(size_t)atom*SEL0 + m]; s = g_dist0[(size_t)atom*SEL0 + m]; }
        else         { j = g_idx1[(size_t)atom*SEL1 + (m-SEL0)]; s = g_dist1[(size_t)atom*SEL1 + (m-SEL0)]; }
        float gR = gd[m];
        float invr = 1.0f/(s + EPSF);
        float cf = -gR*invr*invr / s;
        float rx = mic(xi - xb[3*j+0] + EPSF);
        float ry = mic(yi - xb[3*j+1] + EPSF);
        float rz = mic(zi - xb[3*j+2] + EPSF);
        float gtx = cf*rx, gty = cf*ry, gtz = cf*rz;
        atomicAdd(&gi[0], gtx); atomicAdd(&gi[1], gty); atomicAdd(&gi[2], gtz);
        atomicAdd(&gradb[3*j+0], -gtx);
        atomicAdd(&gradb[3*j+1], -gty);
        atomicAdd(&gradb[3*j+2], -gtz);
    }
    __syncthreads();

    if (tid == 0){
        float g0x=G[0], g0y=G[1], g0z=G[2];
        float g1x=G[3], g1y=G[4], g1z=G[5];
        float g2x=G[6], g2y=G[7], g2z=G[8];

        float dr0x = g0x, dr0y = g0y, dr0z = g0z;
        float dr1x = 0.f, dr1y = 0.f, dr1z = 0.f;

        float t1 = g1x*f.v2x + g1y*f.v2y + g1z*f.v2z;
        float invnp = 1.0f/f.np;
        float gpx = (g1x - t1*f.v2x)*invnp;
        float gpy = (g1y - t1*f.v2y)*invnp;
        float gpz = (g1z - t1*f.v2z)*invnp;
        float gpr0 = gpx*f.r0x + gpy*f.r0y + gpz*f.r0z;
        dr1x += gpx - gpr0*f.r0x;
        dr1y += gpy - gpr0*f.r0y;
        dr1z += gpz - gpr0*f.r0z;
        dr0x += -f.s*gpx - gpr0*f.r1x;
        dr0y += -f.s*gpy - gpr0*f.r1y;
        dr0z += -f.s*gpz - gpr0*f.r1z;

        float t2 = g2x*f.v3x + g2y*f.v3y + g2z*f.v3z;
        float invnc = 1.0f/f.nc;
        float gcx = (g2x - t2*f.v3x)*invnc;
        float gcy = (g2y - t2*f.v3y)*invnc;
        float gcz = (g2z - t2*f.v3z)*invnc;
        dr0x += f.r1y*gcz - f.r1z*gcy;
        dr0y += f.r1z*gcx - f.r1x*gcz;
        dr0z += f.r1x*gcy - f.r1y*gcx;
        dr1x += gcy*f.r0z - gcz*f.r0y;
        dr1y += gcz*f.r0x - gcx*f.r0z;
        dr1z += gcx*f.r0y - gcy*f.r0x;

        float dd0 = (dr0x*f.rv0x + dr0y*f.rv0y + dr0z*f.rv0z) * (-f.inv0*f.inv0);
        float c0 = dd0 / f.d0;
        float gt0x = dr0x*f.inv0 + c0*f.rv0x;
        float gt0y = dr0y*f.inv0 + c0*f.rv0y;
        float gt0z = dr0z*f.inv0 + c0*f.rv0z;
        atomicAdd(&gradb[3*f.j0+0], -gt0x);
        atomicAdd(&gradb[3*f.j0+1], -gt0y);
        atomicAdd(&gradb[3*f.j0+2], -gt0z);

        float dd1 = (dr1x*f.rv1x + dr1y*f.rv1y + dr1z*f.rv1z) * (-f.inv1*f.inv1);
        float c1 = dd1 / f.d1;
        float gt1x = dr1x*f.inv1 + c1*f.rv1x;
        float gt1y = dr1y*f.inv1 + c1*f.rv1y;
        float gt1z = dr1z*f.inv1 + c1*f.rv1z;
        atomicAdd(&gradb[3*f.j1+0], -gt1x);
        atomicAdd(&gradb[3*f.j1+1], -gt1y);
        atomicAdd(&gradb[3*f.j1+2], -gt1z);

        atomicAdd(&gradb[3*i+0], gi[0] + gt0x + gt1x);
        atomicAdd(&gradb[3*i+1], gi[1] + gt0y + gt1y);
        atomicAdd(&gradb[3*i+2], gi[2] + gt0z + gt1z);
    }
}

// ---------------------------------------------------------------------------
// Output kernels
// ---------------------------------------------------------------------------
__global__ void zero_kernel(){
    int idx = blockIdx.x*blockDim.x + threadIdx.x;
    if (idx < NATOMS*3) g_grad[idx] = 0.0f;
}

__global__ void energy_kernel(float* __restrict__ out){
    __shared__ float red[256];
    int b = blockIdx.x, tid = threadIdx.x;
    float acc = 0.0f;
    for (int i2 = tid; i2 < NA; i2 += 256) acc += g_e[b*NA + i2];
    red[tid] = acc;
    __syncthreads();
    for (int off = 128; off > 0; off >>= 1){
        if (tid < off) red[tid] += red[tid + off];
        __syncthreads();
    }
    if (tid == 0) out[b] = red[0];
}

__global__ void force_kernel(float* __restrict__ out){
    int idx = blockIdx.x*blockDim.x + threadIdx.x;
    if (idx < NATOMS*3) out[2 + idx] = -g_grad[idx];
}

// ---------------------------------------------------------------------------
extern "C" void kernel_launch(void* const* d_in, const int* in_sizes, int n_in,
                              void* d_out, int out_size){
    const float* xyz   = (const float*)d_in[0];
    const int*   types = (const int*)  d_in[1];
    const float* W00=(const float*)d_in[3],  *b00=(const float*)d_in[4];
    const float* W01=(const float*)d_in[5],  *b01=(const float*)d_in[6];
    const float* W02=(const float*)d_in[7],  *b02=(const float*)d_in[8];
    const float* W10=(const float*)d_in[9],  *b10=(const float*)d_in[10];
    const float* W11=(const float*)d_in[11], *b11=(const float*)d_in[12];
    const float* W12=(const float*)d_in[13], *b12=(const float*)d_in[14];
    float* out = (float*)d_out;

    zero_kernel<<<(NATOMS*3 + 255)/256, 256>>>();
    transpose_kernel<<<(2*DDIM*HID + 255)/256, 256>>>(W00, W10, W01, W11);
    knn_kernel<<<NATOMS, 256>>>(xyz, types);
    desc_kernel<<<NATOMS, 64>>>(xyz);
    fwd1_kernel<<<NATOMS/AF, AF*HID>>>(types, W00, b00, W10, b10);
    fwd2_kernel<<<NATOMS/AF, AF*HID>>>(types, W01, b01, W11, b11,
                                              W02, b02, W12, b12);
    bwd1_kernel<<<NATOMS/AF, AF*HID>>>(types);
    bwd2_kernel<<<(int)(((long long)NATOMS*DDIM + 255)/256), 256>>>(types);
    bwd_kernel<<<NATOMS, 64>>>(xyz);
    energy_kernel<<<BB, 256>>>(out);
    force_kernel<<<(NATOMS*3 + 255)/256, 256>>>(out);
}

// round 5
// speedup vs baseline: 8.8241x; 1.4251x over previous
#include <cuda_runtime.h>
#include <math.h>

#define BB 2
#define NA 2048
#define NATOMS (BB*NA)
#define BOXF 27.0f
#define SEL0 46
#define SEL1 92
#define ASEL0 16
#define ASEL1 32
#define NANG (ASEL0+ASEL1)      /* 48  */
#define NRAD (SEL0+SEL1)        /* 138 */
#define DDIM (NRAD + 3*NANG)    /* 282 */
#define HID 64
#define EPSF 1e-16f
#define FULLM 0xFFFFFFFFu

/* warp-knn params */
#define WPB 8                 /* warps (atoms) per block  */
#define NBINW 128
#define BSCALEW 9.375f        /* 128 bins over [0,13.65]  */
#define CAPW0 96
#define CAPW1 160

__device__ float g_dist0[NATOMS*SEL0];
__device__ int   g_idx0 [NATOMS*SEL0];
__device__ float g_dist1[NATOMS*SEL1];
__device__ int   g_idx1 [NATOMS*SEL1];
__device__ float g_desc [NATOMS*DDIM];
__device__ float g_gdesc[NATOMS*DDIM];
__device__ float g_grad [NATOMS*3];
__device__ float g_e    [NATOMS];
__device__ float g_W0T  [2*HID*DDIM];   /* [t][s][d] */
__device__ float g_W1T  [2*HID*HID];    /* [t][s][c] */

__device__ __forceinline__ float mic(float d){
    return d - BOXF * rintf(d * (1.0f/BOXF));
}
__device__ __forceinline__ float wred(float v){
    v += __shfl_xor_sync(FULLM, v, 16);
    v += __shfl_xor_sync(FULLM, v, 8);
    v += __shfl_xor_sync(FULLM, v, 4);
    v += __shfl_xor_sync(FULLM, v, 2);
    v += __shfl_xor_sync(FULLM, v, 1);
    return v;
}

// ---------------------------------------------------------------------------
// K1: warp-per-atom kNN. histogram-select + ballot compaction + rank sort.
// ---------------------------------------------------------------------------
__global__ void knn_kernel(const float* __restrict__ xyz, const int* __restrict__ types){
    __shared__ float sx[NA], sy[NA], sz[NA];
    __shared__ unsigned char st[NA];
    __shared__ unsigned int hist[WPB][NBINW];
    __shared__ unsigned long long c0buf[WPB][CAPW0];
    __shared__ unsigned long long c1buf[WPB][CAPW1];

    int tid = threadIdx.x;
    int w = tid >> 5, lane = tid & 31;
    int atom = blockIdx.x*WPB + w;
    int b = atom >> 11, i = atom & (NA-1);
    const float* xb = xyz + (size_t)b*NA*3;
    const int* tb = types + (size_t)b*NA;

    for (int j = tid; j < NA; j += WPB*32){
        sx[j] = xb[3*j+0]; sy[j] = xb[3*j+1]; sz[j] = xb[3*j+2];
        st[j] = (unsigned char)tb[j];
    }
    __syncthreads();

    float xi = sx[i], yi = sy[i], zi = sz[i];

    /* zero my warp's histogram */
    #pragma unroll
    for (int q = 0; q < NBINW/32; q++) hist[w][lane + 32*q] = 0;
    __syncwarp();

    /* pass 1: histogram (packed: low16=type0, high16=type1) */
    for (int j = lane; j < NA; j += 32){
        if (j == i) continue;
        float dx = mic(xi - sx[j] + EPSF);
        float dy = mic(yi - sy[j] + EPSF);
        float dz = mic(zi - sz[j] + EPSF);
        float d = sqrtf(dx*dx + dy*dy + dz*dz);
        int bn = (int)(d * BSCALEW); if (bn > NBINW-1) bn = NBINW-1;
        atomicAdd(&hist[w][bn], st[j] ? 0x10000u : 1u);
    }
    __syncwarp();

    /* threshold scan: lane covers bins [4l,4l+4) */
    unsigned chunk = 0;
    #pragma unroll
    for (int q = 0; q < 4; q++) chunk += hist[w][4*lane + q];
    unsigned incl = chunk;
    #pragma unroll
    for (int off = 1; off < 32; off <<= 1){
        unsigned v = __shfl_up_sync(FULLM, incl, off);
        if (lane >= off) incl += v;
    }
    unsigned excl = incl - chunk;

    int thr0, thr1;
    {
        unsigned m0 = __ballot_sync(FULLM, (incl & 0xFFFFu) >= SEL0);
        int fl = __ffs(m0) - 1;
        int tl = 0;
        if (lane == fl){
            int c = (int)(excl & 0xFFFFu);
            int bq = 4*lane;
            #pragma unroll
            for (int q = 0; q < 4; q++){
                c += (int)(hist[w][bq] & 0xFFFFu);
                if (c >= SEL0) break;
                bq++;
            }
            tl = bq;
        }
        thr0 = __shfl_sync(FULLM, tl, fl);
    }
    {
        unsigned m1 = __ballot_sync(FULLM, (incl >> 16) >= SEL1);
        int fl = __ffs(m1) - 1;
        int tl = 0;
        if (lane == fl){
            int c = (int)(excl >> 16);
            int bq = 4*lane;
            #pragma unroll
            for (int q = 0; q < 4; q++){
                c += (int)(hist[w][bq] >> 16);
                if (c >= SEL1) break;
                bq++;
            }
            tl = bq;
        }
        thr1 = __shfl_sync(FULLM, tl, fl);
    }

    /* pass 2: ballot compaction */
    unsigned lanelt = (1u << lane) - 1u;
    int cnt0 = 0, cnt1 = 0;
    for (int j = lane; j < NA; j += 32){
        int t = (j == i) ? 2 : (int)st[j];
        float dx = mic(xi - sx[j] + EPSF);
        float dy = mic(yi - sy[j] + EPSF);
        float dz = mic(zi - sz[j] + EPSF);
        float d = sqrtf(dx*dx + dy*dy + dz*dz);
        int bn = (int)(d * BSCALEW); if (bn > NBINW-1) bn = NBINW-1;
        unsigned long long key = ((unsigned long long)__float_as_uint(d) << 11)
                               | (unsigned long long)j;
        bool p0 = (t == 0) && (bn <= thr0);
        bool p1 = (t == 1) && (bn <= thr1);
        unsigned m0 = __ballot_sync(FULLM, p0);
        unsigned m1 = __ballot_sync(FULLM, p1);
        if (p0){ int pos = cnt0 + __popc(m0 & lanelt); if (pos < CAPW0) c0buf[w][pos] = key; }
        if (p1){ int pos = cnt1 + __popc(m1 & lanelt); if (pos < CAPW1) c1buf[w][pos] = key; }
        cnt0 += __popc(m0); cnt1 += __popc(m1);
    }
    if (cnt0 > CAPW0) cnt0 = CAPW0;
    if (cnt1 > CAPW1) cnt1 = CAPW1;
    __syncwarp();

    /* rank sort + write */
    for (int m = lane; m < cnt0; m += 32){
        unsigned long long k64 = c0buf[w][m];
        int r = 0;
        for (int q = 0; q < cnt0; q++) r += (c0buf[w][q] < k64);
        if (r < SEL0){
            g_dist0[(size_t)atom*SEL0 + r] = __uint_as_float((unsigned)(k64 >> 11));
            g_idx0 [(size_t)atom*SEL0 + r] = (int)(k64 & 2047ULL);
        }
    }
    for (int m = lane; m < cnt1; m += 32){
        unsigned long long k64 = c1buf[w][m];
        int r = 0;
        for (int q = 0; q < cnt1; q++) r += (c1buf[w][q] < k64);
        if (r < SEL1){
            g_dist1[(size_t)atom*SEL1 + r] = __uint_as_float((unsigned)(k64 >> 11));
            g_idx1 [(size_t)atom*SEL1 + r] = (int)(k64 & 2047ULL);
        }
    }
}

// ---------------------------------------------------------------------------
// Local frame
// ---------------------------------------------------------------------------
struct Frame {
    float r0x,r0y,r0z, r1x,r1y,r1z;
    float rv0x,rv0y,rv0z, rv1x,rv1y,rv1z;
    float d0, d1, inv0, inv1;
    float s, np, nc;
    float v2x,v2y,v2z, v3x,v3y,v3z;
    int j0, j1;
};

__device__ Frame make_frame(int atom, const float* xb, float xi, float yi, float zi){
    Frame f;
    float s00 = g_dist0[(size_t)atom*SEL0+0], s01 = g_dist0[(size_t)atom*SEL0+1];
    float s10 = g_dist1[(size_t)atom*SEL1+0], s11 = g_dist1[(size_t)atom*SEL1+1];
    int   i00 = g_idx0 [(size_t)atom*SEL0+0], i01 = g_idx0 [(size_t)atom*SEL0+1];
    int   i10 = g_idx1 [(size_t)atom*SEL1+0], i11 = g_idx1 [(size_t)atom*SEL1+1];
    if (s10 < s00){ f.d0 = s10; f.j0 = i10; } else { f.d0 = s00; f.j0 = i00; }
    if (s11 < s01){ f.d1 = s11; f.j1 = i11; } else { f.d1 = s01; f.j1 = i01; }

    f.rv0x = mic(xi - xb[3*f.j0+0] + EPSF);
    f.rv0y = mic(yi - xb[3*f.j0+1] + EPSF);
    f.rv0z = mic(zi - xb[3*f.j0+2] + EPSF);
    f.rv1x = mic(xi - xb[3*f.j1+0] + EPSF);
    f.rv1y = mic(yi - xb[3*f.j1+1] + EPSF);
    f.rv1z = mic(zi - xb[3*f.j1+2] + EPSF);

    f.inv0 = 1.0f/(f.d0 + EPSF);
    f.inv1 = 1.0f/(f.d1 + EPSF);
    f.r0x = f.rv0x*f.inv0; f.r0y = f.rv0y*f.inv0; f.r0z = f.rv0z*f.inv0;
    f.r1x = f.rv1x*f.inv1; f.r1y = f.rv1y*f.inv1; f.r1z = f.rv1z*f.inv1;

    f.s = f.r0x*f.r1x + f.r0y*f.r1y + f.r0z*f.r1z;
    float px = f.r1x - f.s*f.r0x;
    float py = f.r1y - f.s*f.r0y;
    float pz = f.r1z - f.s*f.r0z;
    f.np = sqrtf(px*px + py*py + pz*pz);
    float invnp = 1.0f/f.np;
    f.v2x = px*invnp; f.v2y = py*invnp; f.v2z = pz*invnp;

    float cx = f.r0y*f.r1z - f.r0z*f.r1y;
    float cy = f.r0z*f.r1x - f.r0x*f.r1z;
    float cz = f.r0x*f.r1y - f.r0y*f.r1x;
    f.nc = sqrtf(cx*cx + cy*cy + cz*cz);
    float invnc = 1.0f/f.nc;
    f.v3x = cx*invnc; f.v3y = cy*invnc; f.v3z = cz*invnc;
    return f;
}

// ---------------------------------------------------------------------------
// K2: descriptor forward (warp per atom)
// ---------------------------------------------------------------------------
__global__ void desc_kernel(const float* __restrict__ xyz){
    int tid = threadIdx.x;
    int w = tid >> 5, lane = tid & 31;
    int atom = blockIdx.x*WPB + w;
    int b = atom >> 11, i = atom & (NA-1);
    const float* xb = xyz + (size_t)b*NA*3;
    float xi = xb[3*i+0], yi = xb[3*i+1], zi = xb[3*i+2];

    Frame f = make_frame(atom, xb, xi, yi, zi);
    float A0=f.r0x, A1=f.r0y, A2=f.r0z;
    float A3=f.v2x, A4=f.v2y, A5=f.v2z;
    float A6=f.v3x, A7=f.v3y, A8=f.v3z;

    float* dsc = g_desc + (size_t)atom*DDIM;
    for (int m = lane; m < NRAD; m += 32){
        float s = (m < SEL0) ? g_dist0[(size_t)atom*SEL0 + m]
                             : g_dist1[(size_t)atom*SEL1 + (m - SEL0)];
        dsc[m] = 1.0f/(s + EPSF);
    }
    for (int k = lane; k < NANG; k += 32){
        int j; float d;
        if (k < ASEL0){ j = g_idx0[(size_t)atom*SEL0 + k]; d = g_dist0[(size_t)atom*SEL0 + k]; }
        else          { j = g_idx1[(size_t)atom*SEL1 + (k-ASEL0)]; d = g_dist1[(size_t)atom*SEL1 + (k-ASEL0)]; }
        float rx = mic(xi - xb[3*j+0] + EPSF);
        float ry = mic(yi - xb[3*j+1] + EPSF);
        float rz = mic(zi - xb[3*j+2] + EPSF);
        float inv = 1.0f/(d + EPSF);
        float ww = inv*inv;
        dsc[NRAD + 3*k + 0] = (A0*rx + A1*ry + A2*rz)*ww;
        dsc[NRAD + 3*k + 1] = (A3*rx + A4*ry + A5*rz)*ww;
        dsc[NRAD + 3*k + 2] = (A6*rx + A7*ry + A8*rz)*ww;
    }
}

// ---------------------------------------------------------------------------
// Prep: weight transposes + grad zero
// ---------------------------------------------------------------------------
__global__ void prep_kernel(
    const float* __restrict__ W00, const float* __restrict__ W10,
    const float* __restrict__ W01, const float* __restrict__ W11){
    int idx = blockIdx.x*blockDim.x + threadIdx.x;
    if (idx < 2*DDIM*HID){
        int t = idx / (DDIM*HID);
        int r = idx % (DDIM*HID);
        int d = r / HID, s = r % HID;
        const float* W = t ? W10 : W00;
        g_W0T[t*HID*DDIM + s*DDIM + d] = W[r];
    }
    if (idx < 2*HID*HID){
        int t = idx / (HID*HID);
        int r = idx % (HID*HID);
        int c = r / HID, s = r % HID;
        const float* W = t ? W11 : W01;
        g_W1T[t*HID*HID + s*HID + c] = W[r];
    }
    if (idx < NATOMS*3) g_grad[idx] = 0.0f;
}

// ---------------------------------------------------------------------------
// K3: fused MLP forward + backward (4 atoms per 256-thread block)
// ---------------------------------------------------------------------------
#define AF 4

__global__ void mlp_kernel(const int* __restrict__ types,
    const float* __restrict__ W00, const float* __restrict__ b00,
    const float* __restrict__ W01, const float* __restrict__ b01,
    const float* __restrict__ W02, const float* __restrict__ b02,
    const float* __restrict__ W10, const float* __restrict__ b10,
    const float* __restrict__ W11, const float* __restrict__ b11,
    const float* __restrict__ W12, const float* __restrict__ b12){

    __shared__ float sX[AF][DDIM];
    __shared__ float sH1[AF][HID];
    __shared__ float sG[AF][HID];
    __shared__ float sZ[AF][HID];
    __shared__ float red[AF][HID];

    int tid = threadIdx.x;
    int j = tid & (HID-1), a = tid >> 6;
    int atom = blockIdx.x*AF + a;

    for (int d = tid; d < AF*DDIM; d += AF*HID)
        sX[d/DDIM][d%DDIM] = g_desc[(size_t)blockIdx.x*AF*DDIM + d];
    __syncthreads();

    int t = types[atom];
    const float* W0 = t ? W10 : W00;
    const float* W1 = t ? W11 : W01;

    float acc0 = (t ? b10 : b00)[j], acc1 = 0.0f;
    const float* xr = sX[a];
    #pragma unroll 2
    for (int d = 0; d < DDIM; d += 2){
        acc0 = fmaf(xr[d],   W0[d*HID + j],     acc0);
        acc1 = fmaf(xr[d+1], W0[(d+1)*HID + j], acc1);
    }
    float h1 = tanhf(acc0 + acc1);
    sH1[a][j] = h1;
    __syncthreads();

    float acc = (t ? b11 : b01)[j];
    const float* hr = sH1[a];
    #pragma unroll 4
    for (int s = 0; s < HID; s++) acc = fmaf(hr[s], W1[s*HID + j], acc);
    float h2 = tanhf(acc);
    float w2 = t ? W12[j] : W02[j];
    red[a][j] = h2 * w2;
    sG[a][j]  = w2 * (1.0f - h2*h2);
    __syncthreads();

    for (int off = HID/2; off > 0; off >>= 1){
        if (j < off) red[a][j] += red[a][j + off];
        __syncthreads();
    }
    if (j == 0) g_e[atom] = red[a][0] + (t ? b12[0] : b02[0]);

    /* bwd1: gz1 = (W1 . gh2) * (1-h1^2)  via W1T */
    const float* W1T = g_W1T + (size_t)t*HID*HID;
    const float* gr = sG[a];
    float ag = 0.0f;
    #pragma unroll 4
    for (int s = 0; s < HID; s++) ag = fmaf(gr[s], W1T[s*HID + j], ag);
    sZ[a][j] = ag * (1.0f - h1*h1);
    __syncthreads();

    /* bwd2: gdesc = W0T . gz1 */
    const float* W0T = g_W0T + (size_t)t*HID*DDIM;
    const float* zr = sZ[a];
    for (int d = j; d < DDIM; d += HID){
        float g = 0.0f;
        #pragma unroll 4
        for (int s = 0; s < HID; s++) g = fmaf(zr[s], W0T[s*DDIM + d], g);
        g_gdesc[(size_t)atom*DDIM + d] = g;
    }
}

// ---------------------------------------------------------------------------
// K4: descriptor backward (warp per atom, register G + shuffle reduce)
// ---------------------------------------------------------------------------
__global__ void bwd_kernel(const float* __restrict__ xyz){
    int tid = threadIdx.x;
    int w = tid >> 5, lane = tid & 31;
    int atom = blockIdx.x*WPB + w;
    int b = atom >> 11, i = atom & (NA-1);
    const float* xb = xyz + (size_t)b*NA*3;
    float xi = xb[3*i+0], yi = xb[3*i+1], zi = xb[3*i+2];

    Frame f = make_frame(atom, xb, xi, yi, zi);
    float A0=f.r0x, A1=f.r0y, A2=f.r0z;
    float A3=f.v2x, A4=f.v2y, A5=f.v2z;
    float A6=f.v3x, A7=f.v3y, A8=f.v3z;

    const float* gd = g_gdesc + (size_t)atom*DDIM;
    float* gradb = g_grad + (size_t)b*NA*3;

    float G0=0,G1=0,G2=0,G3=0,G4=0,G5=0,G6=0,G7=0,G8=0;
    float gix=0, giy=0, giz=0;

    for (int k = lane; k < NANG; k += 32){
        int j; float dN;
        if (k < ASEL0){ j = g_idx0[(size_t)atom*SEL0 + k]; dN = g_dist0[(size_t)atom*SEL0 + k]; }
        else          { j = g_idx1[(size_t)atom*SEL1 + (k-ASEL0)]; dN = g_dist1[(size_t)atom*SEL1 + (k-ASEL0)]; }
        float rx = mic(xi - xb[3*j+0] + EPSF);
        float ry = mic(yi - xb[3*j+1] + EPSF);
        float rz = mic(zi - xb[3*j+2] + EPSF);
        float gx = gd[NRAD + 3*k + 0];
        float gy = gd[NRAD + 3*k + 1];
        float gz3= gd[NRAD + 3*k + 2];
        float inv = 1.0f/(dN + EPSF);
        float ww = inv*inv;
        float Arx = A0*rx + A1*ry + A2*rz;
        float Ary = A3*rx + A4*ry + A5*rz;
        float Arz = A6*rx + A7*ry + A8*rz;
        float gvx = (A0*gx + A3*gy + A6*gz3)*ww;
        float gvy = (A1*gx + A4*gy + A7*gz3)*ww;
        float gvz = (A2*gx + A5*gy + A8*gz3)*ww;
        float gdd = (gx*Arx + gy*Ary + gz3*Arz) * (-2.0f*ww*inv);
        G0 += ww*gx*rx;  G1 += ww*gx*ry;  G2 += ww*gx*rz;
        G3 += ww*gy*rx;  G4 += ww*gy*ry;  G5 += ww*gy*rz;
        G6 += ww*gz3*rx; G7 += ww*gz3*ry; G8 += ww*gz3*rz;
        float cf = gdd / dN;
        float gtx = gvx + cf*rx, gty = gvy + cf*ry, gtz = gvz + cf*rz;
        gix += gtx; giy += gty; giz += gtz;
        atomicAdd(&gradb[3*j+0], -gtx);
        atomicAdd(&gradb[3*j+1], -gty);
        atomicAdd(&gradb[3*j+2], -gtz);
    }

    for (int m = lane; m < NRAD; m += 32){
        int j; float s;
        if (m < SEL0){ j = g_idx0[(size_t)atom*SEL0 + m]; s = g_dist0[(size_t)atom*SEL0 + m]; }
        else         { j = g_idx1[(size_t)atom*SEL1 + (m-SEL0)]; s = g_dist1[(size_t)atom*SEL1 + (m-SEL0)]; }
        float gR = gd[m];
        float invr = 1.0f/(s + EPSF);
        float cf = -gR*invr*invr / s;
        float rx = mic(xi - xb[3*j+0] + EPSF);
        float ry = mic(yi - xb[3*j+1] + EPSF);
        float rz = mic(zi - xb[3*j+2] + EPSF);
        float gtx = cf*rx, gty = cf*ry, gtz = cf*rz;
        gix += gtx; giy += gty; giz += gtz;
        atomicAdd(&gradb[3*j+0], -gtx);
        atomicAdd(&gradb[3*j+1], -gty);
        atomicAdd(&gradb[3*j+2], -gtz);
    }

    G0 = wred(G0); G1 = wred(G1); G2 = wred(G2);
    G3 = wred(G3); G4 = wred(G4); G5 = wred(G5);
    G6 = wred(G6); G7 = wred(G7); G8 = wred(G8);
    gix = wred(gix); giy = wred(giy); giz = wred(giz);

    if (lane == 0){
        float dr0x = G0, dr0y = G1, dr0z = G2;
        float dr1x = 0.f, dr1y = 0.f, dr1z = 0.f;

        float t1 = G3*f.v2x + G4*f.v2y + G5*f.v2z;
        float invnp = 1.0f/f.np;
        float gpx = (G3 - t1*f.v2x)*invnp;
        float gpy = (G4 - t1*f.v2y)*invnp;
        float gpz = (G5 - t1*f.v2z)*invnp;
        float gpr0 = gpx*f.r0x + gpy*f.r0y + gpz*f.r0z;
        dr1x += gpx - gpr0*f.r0x;
        dr1y += gpy - gpr0*f.r0y;
        dr1z += gpz - gpr0*f.r0z;
        dr0x += -f.s*gpx - gpr0*f.r1x;
        dr0y += -f.s*gpy - gpr0*f.r1y;
        dr0z += -f.s*gpz - gpr0*f.r1z;

        float t2 = G6*f.v3x + G7*f.v3y + G8*f.v3z;
        float invnc = 1.0f/f.nc;
        float gcx = (G6 - t2*f.v3x)*invnc;
        float gcy = (G7 - t2*f.v3y)*invnc;
        float gcz = (G8 - t2*f.v3z)*invnc;
        dr0x += f.r1y*gcz - f.r1z*gcy;
        dr0y += f.r1z*gcx - f.r1x*gcz;
        dr0z += f.r1x*gcy - f.r1y*gcx;
        dr1x += gcy*f.r0z - gcz*f.r0y;
        dr1y += gcz*f.r0x - gcx*f.r0z;
        dr1z += gcx*f.r0y - gcy*f.r0x;

        float dd0 = (dr0x*f.rv0x + dr0y*f.rv0y + dr0z*f.rv0z) * (-f.inv0*f.inv0);
        float c0 = dd0 / f.d0;
        float gt0x = dr0x*f.inv0 + c0*f.rv0x;
        float gt0y = dr0y*f.inv0 + c0*f.rv0y;
        float gt0z = dr0z*f.inv0 + c0*f.rv0z;
        atomicAdd(&gradb[3*f.j0+0], -gt0x);
        atomicAdd(&gradb[3*f.j0+1], -gt0y);
        atomicAdd(&gradb[3*f.j0+2], -gt0z);

        float dd1 = (dr1x*f.rv1x + dr1y*f.rv1y + dr1z*f.rv1z) * (-f.inv1*f.inv1);
        float c1 = dd1 / f.d1;
        float gt1x = dr1x*f.inv1 + c1*f.rv1x;
        float gt1y = dr1y*f.inv1 + c1*f.rv1y;
        float gt1z = dr1z*f.inv1 + c1*f.rv1z;
        atomicAdd(&gradb[3*f.j1+0], -gt1x);
        atomicAdd(&gradb[3*f.j1+1], -gt1y);
        atomicAdd(&gradb[3*f.j1+2], -gt1z);

        atomicAdd(&gradb[3*i+0], gix + gt0x + gt1x);
        atomicAdd(&gradb[3*i+1], giy + gt0y + gt1y);
        atomicAdd(&gradb[3*i+2], giz + gt0z + gt1z);
    }
}

// ---------------------------------------------------------------------------
// Output: forces (blocks 0..47) + energies (blocks 48,49)
// ---------------------------------------------------------------------------
__global__ void out_kernel(float* __restrict__ out){
    if (blockIdx.x < 48){
        int idx = blockIdx.x*256 + threadIdx.x;
        if (idx < NATOMS*3) out[2 + idx] = -g_grad[idx];
    } else {
        __shared__ float red[256];
        int b = blockIdx.x - 48;
        int tid = threadIdx.x;
        float acc = 0.0f;
        for (int i2 = tid; i2 < NA; i2 += 256) acc += g_e[b*NA + i2];
        red[tid] = acc;
        __syncthreads();
        for (int off = 128; off > 0; off >>= 1){
            if (tid < off) red[tid] += red[tid + off];
            __syncthreads();
        }
        if (tid == 0) out[b] = red[0];
    }
}

// ---------------------------------------------------------------------------
extern "C" void kernel_launch(void* const* d_in, const int* in_sizes, int n_in,
                              void* d_out, int out_size){
    const float* xyz   = (const float*)d_in[0];
    const int*   types = (const int*)  d_in[1];
    const float* W00=(const float*)d_in[3],  *b00=(const float*)d_in[4];
    const float* W01=(const float*)d_in[5],  *b01=(const float*)d_in[6];
    const float* W02=(const float*)d_in[7],  *b02=(const float*)d_in[8];
    const float* W10=(const float*)d_in[9],  *b10=(const float*)d_in[10];
    const float* W11=(const float*)d_in[11], *b11=(const float*)d_in[12];
    const float* W12=(const float*)d_in[13], *b12=(const float*)d_in[14];
    float* out = (float*)d_out;

    prep_kernel<<<(2*DDIM*HID + 255)/256, 256>>>(W00, W10, W01, W11);
    knn_kernel<<<NATOMS/WPB, WPB*32>>>(xyz, types);
    desc_kernel<<<NATOMS/WPB, WPB*32>>>(xyz);
    mlp_kernel<<<NATOMS/AF, AF*HID>>>(types, W00,b00,W01,b01,W02,b02,
                                             W10,b10,W11,b11,W12,b12);
    bwd_kernel<<<NATOMS/WPB, WPB*32>>>(xyz);
    out_kernel<<<50, 256>>>(out);
}